// round 9
// baseline (speedup 1.0000x reference)
#include <cuda_runtime.h>
#include <cstdint>

// Problem constants
#define B_  4
#define T_  2048
#define D_  1024
#define H_  16
#define HD_ 64
#define M_  (B_*T_)   // 8192

// Scratch buffers
__device__ float g_q[(size_t)B_*H_*T_*HD_];
__device__ float g_k[(size_t)B_*H_*T_*HD_];
__device__ float g_v[(size_t)B_*H_*T_*HD_];
__device__ float g_o[(size_t)B_*T_*D_];
__device__ float g_xr[(size_t)B_*T_*D_];     // tf32-rounded activations
__device__ float g_wr[(size_t)4*D_*D_];      // tf32-rounded weights (k,q,v,p)

// ---------------------------------------------------------------------------
// helpers
// ---------------------------------------------------------------------------
__device__ __forceinline__ uint32_t smem_u32(const void* p) {
    uint32_t a;
    asm("{ .reg .u64 t; cvta.to.shared.u64 t, %1; cvt.u32.u64 %0, t; }"
        : "=r"(a) : "l"(p));
    return a;
}

__device__ __forceinline__ void cp_async16(uint32_t dst, const void* src) {
    asm volatile("cp.async.cg.shared.global [%0], [%1], 16;" :: "r"(dst), "l"(src));
}

__device__ __forceinline__ void mma_tf32(float* c, const uint32_t* a, const uint32_t* b) {
    asm volatile(
        "mma.sync.aligned.m16n8k8.row.col.f32.tf32.tf32.f32 "
        "{%0,%1,%2,%3}, {%4,%5,%6,%7}, {%8,%9}, {%0,%1,%2,%3};"
        : "+f"(c[0]), "+f"(c[1]), "+f"(c[2]), "+f"(c[3])
        : "r"(a[0]), "r"(a[1]), "r"(a[2]), "r"(a[3]), "r"(b[0]), "r"(b[1]));
}

__device__ __forceinline__ void mma_tf32_b(float* c, const uint32_t* a,
                                           uint32_t b0, uint32_t b1) {
    asm volatile(
        "mma.sync.aligned.m16n8k8.row.col.f32.tf32.tf32.f32 "
        "{%0,%1,%2,%3}, {%4,%5,%6,%7}, {%8,%9}, {%0,%1,%2,%3};"
        : "+f"(c[0]), "+f"(c[1]), "+f"(c[2]), "+f"(c[3])
        : "r"(a[0]), "r"(a[1]), "r"(a[2]), "r"(a[3]), "r"(b0), "r"(b1));
}

__device__ __forceinline__ float rna_tf32(float x) {
    uint32_t u;
    asm("cvt.rna.tf32.f32 %0, %1;" : "=r"(u) : "f"(x));
    return __uint_as_float(u);
}

// ---------------------------------------------------------------------------
// tf32 pre-rounding
// ---------------------------------------------------------------------------
__global__ void __launch_bounds__(256) round_tf32(const float* __restrict__ x,
                                                  float* __restrict__ y) {
    const size_t i = ((size_t)blockIdx.x * 256 + threadIdx.x) * 4;
    float4 v = *(const float4*)(x + i);
    float4 o;
    o.x = rna_tf32(v.x); o.y = rna_tf32(v.y);
    o.z = rna_tf32(v.z); o.w = rna_tf32(v.w);
    *(float4*)(y + i) = o;
}

struct WPtrs { const float* w[4]; };
__global__ void __launch_bounds__(256) round_w4(WPtrs ws, float* __restrict__ y) {
    const int z = blockIdx.y;
    const float* src = ws.w[z];
    float* dst = y + (size_t)z * D_ * D_;
    const size_t i = ((size_t)blockIdx.x * 256 + threadIdx.x) * 4;
    float4 v = *(const float4*)(src + i);
    float4 o;
    o.x = rna_tf32(v.x); o.y = rna_tf32(v.y);
    o.z = rna_tf32(v.z); o.w = rna_tf32(v.w);
    *(float4*)(dst + i) = o;
}

// ---------------------------------------------------------------------------
// GEMM (unchanged from round 8 — known good)
// ---------------------------------------------------------------------------
#define SROW   36
#define STG_F  (128 * SROW)
#define STAGE_F (2 * STG_F)
#define GSMEM  (3 * STAGE_F * 4)   // 110592 B

template<int MODE>
__device__ __forceinline__ void gemm_body(const float* __restrict__ A,
                                          const float* __restrict__ W,
                                          float* __restrict__ out,
                                          const float* __restrict__ bias,
                                          float* sm, int bx, int by) {
    const int tid  = threadIdx.x;
    const int lane = tid & 31;
    const int wid  = tid >> 5;
    const int wm   = wid >> 1;
    const int wn   = wid & 1;

    float c[4][8][4];
#pragma unroll
    for (int i = 0; i < 4; i++)
#pragma unroll
        for (int j = 0; j < 8; j++)
#pragma unroll
            for (int k = 0; k < 4; k++) c[i][j][k] = 0.f;

    const int lr = tid >> 3;
    const int ls = tid & 7;
    const float* Ag = A + (size_t)(by * 128 + lr) * 1024 + ls * 4;
    const float* Wg = W + (size_t)(bx * 128 + lr) * 1024 + ls * 4;

    const uint32_t ldst = smem_u32(sm) + (lr * SROW + ls * 4) * 4;

    auto load_tile = [&](int kt, int s) {
        const uint32_t aB = ldst + (uint32_t)s * (STAGE_F * 4);
        const uint32_t bB = aB + STG_F * 4;
        const float* Ak = Ag + kt * 32;
        const float* Wk = Wg + kt * 32;
#pragma unroll
        for (int i = 0; i < 8; i++) {
            cp_async16(aB + i * 16 * (SROW * 4), Ak + (size_t)i * 16 * 1024);
            cp_async16(bB + i * 16 * (SROW * 4), Wk + (size_t)i * 16 * 1024);
        }
        asm volatile("cp.async.commit_group;" ::: "memory");
    };

    load_tile(0, 0);
    load_tile(1, 1);

    const int g = lane >> 2;
    const int q = lane & 3;

    uint32_t af[2][4][4], bf[2][8][2];

    auto frag_load = [&](const uint32_t* As, const uint32_t* Bs, int ks, int buf) {
        const int k0 = ks * 8 + q;
#pragma unroll
        for (int mm = 0; mm < 4; mm++) {
            af[buf][mm][0] = As[(mm * 16)     * SROW + k0];
            af[buf][mm][1] = As[(mm * 16 + 8) * SROW + k0];
            af[buf][mm][2] = As[(mm * 16)     * SROW + k0 + 4];
            af[buf][mm][3] = As[(mm * 16 + 8) * SROW + k0 + 4];
        }
#pragma unroll
        for (int nn = 0; nn < 8; nn++) {
            bf[buf][nn][0] = Bs[(nn * 8) * SROW + k0];
            bf[buf][nn][1] = Bs[(nn * 8) * SROW + k0 + 4];
        }
    };

    int s = 0, sl = 2;
    for (int kt = 0; kt < 32; kt++) {
        if (kt < 31) {
            asm volatile("cp.async.wait_group 1;" ::: "memory");
        } else {
            asm volatile("cp.async.wait_group 0;" ::: "memory");
        }
        __syncthreads();

        if (kt + 2 < 32) {
            load_tile(kt + 2, sl);
            sl = (sl == 2) ? 0 : sl + 1;
        }

        const uint32_t* As = (const uint32_t*)(sm + s * STAGE_F) +
                             (wm * 64 + g) * SROW;
        const uint32_t* Bs = (const uint32_t*)(sm + s * STAGE_F + STG_F) +
                             (wn * 64 + g) * SROW;

        frag_load(As, Bs, 0, 0);
#pragma unroll
        for (int ks = 0; ks < 4; ks++) {
            const int cur = ks & 1;
            if (ks < 3) frag_load(As, Bs, ks + 1, cur ^ 1);
#pragma unroll
            for (int mm = 0; mm < 4; mm++)
#pragma unroll
                for (int nn = 0; nn < 8; nn++)
                    mma_tf32(c[mm][nn], af[cur][mm], bf[cur][nn]);
        }
        s = (s == 2) ? 0 : s + 1;
    }

    const int rbase = by * 128 + wm * 64 + g;
    const int cbase = bx * 128 + wn * 64 + 2 * q;
#pragma unroll
    for (int mm = 0; mm < 4; mm++) {
        const int r0 = rbase + mm * 16;
#pragma unroll
        for (int nn = 0; nn < 8; nn++) {
            const int cc = cbase + nn * 8;
            if (MODE == 0) {
                const int h = cc >> 6, d = cc & 63;
                const int b = r0 >> 11, t = r0 & 2047;
                float* dst = out + (((size_t)(b * H_ + h)) * T_ + t) * HD_ + d;
                *(float2*)dst =
                    make_float2(rna_tf32(c[mm][nn][0]), rna_tf32(c[mm][nn][1]));
                *(float2*)(dst + 8 * HD_) =
                    make_float2(rna_tf32(c[mm][nn][2]), rna_tf32(c[mm][nn][3]));
            } else {
                float2 bb = *(const float2*)(bias + cc);
                float* dst = out + (size_t)r0 * 1024 + cc;
                *(float2*)dst = make_float2(c[mm][nn][0] + bb.x, c[mm][nn][1] + bb.y);
                *(float2*)(dst + 8 * 1024) =
                    make_float2(c[mm][nn][2] + bb.x, c[mm][nn][3] + bb.y);
            }
        }
    }
}

__global__ void __launch_bounds__(128) gemm_qkv(const float* __restrict__ A,
                                                const float* __restrict__ Wr,
                                                float* __restrict__ o0,
                                                float* __restrict__ o1,
                                                float* __restrict__ o2) {
    extern __shared__ float sm[];
    const int z = blockIdx.z;
    const float* W = Wr + (size_t)z * D_ * D_;
    float* out = (z == 0) ? o0 : (z == 1) ? o1 : o2;
    gemm_body<0>(A, W, out, nullptr, sm, blockIdx.x, blockIdx.y);
}

__global__ void __launch_bounds__(128) gemm_out(const float* __restrict__ A,
                                                const float* __restrict__ W,
                                                float* __restrict__ out,
                                                const float* __restrict__ bias) {
    extern __shared__ float sm[];
    gemm_body<1>(A, W, out, bias, sm, blockIdx.x, blockIdx.y);
}

// ---------------------------------------------------------------------------
// Flash attention v2: 2 CTAs/SM.  Q resident in smem (no qf regs),
// single-buffered K (cp.async), V loaded+transposed per tile (transient regs).
// smem = Qs 34816 + Ks 17408 + Vt 17408 + Ps 34816 = 104448 B.
// ---------------------------------------------------------------------------
#define PADK 68
#define KS_F (64 * PADK)
#define QS_F (128 * PADK)
#define FL_SMEM ((QS_F + 2 * KS_F + QS_F) * 4)   // 104448

__global__ void __launch_bounds__(256, 2) flash_mma() {
    extern __shared__ float sm[];
    float* Qs = sm;                       // [128][PADK] queries (resident)
    float* Ks = sm + QS_F;                // [64][PADK]  keys (single buffer)
    float* Vt = sm + QS_F + KS_F;         // [64][PADK]  (d, key) transposed
    float* Ps = sm + QS_F + 2 * KS_F;     // [128][PADK] P

    const int tid = threadIdx.x, lane = tid & 31, wid = tid >> 5;
    const int g = lane >> 2, q = lane & 3;
    const int qt = blockIdx.x, bh = blockIdx.y;
    const int w16 = wid * 16;

    const float* Qg = g_q + (size_t)bh * T_ * HD_ + (size_t)qt * 128 * HD_;
    const float* Kg = g_k + (size_t)bh * T_ * HD_;
    const float* Vg = g_v + (size_t)bh * T_ * HD_;

    const uint32_t sb  = smem_u32(sm);
    const uint32_t KsB = sb + QS_F * 4;

    // prologue: Q -> Qs via cp.async (contiguous rows, stride PADK)
    {
        const int row = tid >> 1, segb = (tid & 1) * 8;
#pragma unroll
        for (int i = 0; i < 8; i++)
            cp_async16(sb + (row * PADK + (segb + i) * 4) * 4,
                       Qg + row * 64 + (segb + i) * 4);
        asm volatile("cp.async.commit_group;" ::: "memory");
    }

    float o_[8][4];
#pragma unroll
    for (int j = 0; j < 8; j++)
#pragma unroll
        for (int k = 0; k < 4; k++) o_[j][k] = 0.f;
    float m0 = -1e30f, m1 = -1e30f, l0 = 0.f, l1 = 0.f;

    const int vr = tid & 63, vqr = tid >> 6;
    const int nkt = 2 * qt + 2;

    for (int kt = 0; kt < nkt; kt++) {
        if (kt > 0) __syncthreads();   // prior tile's Ks/Vt reads complete

        // K(kt) via cp.async (contiguous, stride PADK)
        {
            const float* Kt = Kg + (size_t)kt * 64 * 64;
#pragma unroll
            for (int i = 0; i < 4; i++) {
                const int idx = tid + i * 256;
                cp_async16(KsB + ((idx >> 4) * PADK + (idx & 15) * 4) * 4,
                           Kt + (idx >> 4) * 64 + (idx & 15) * 4);
            }
            asm volatile("cp.async.commit_group;" ::: "memory");
        }
        // V(kt): LDG -> STS transposed (transient regs)
        {
            const float* Vn = Vg + (size_t)kt * 64 * 64;
#pragma unroll
            for (int i = 0; i < 4; i++) {
                float4 v = *(const float4*)(Vn + vr * 64 + vqr * 16 + i * 4);
                Vt[(vqr * 16 + i * 4 + 0) * PADK + vr] = v.x;
                Vt[(vqr * 16 + i * 4 + 1) * PADK + vr] = v.y;
                Vt[(vqr * 16 + i * 4 + 2) * PADK + vr] = v.z;
                Vt[(vqr * 16 + i * 4 + 3) * PADK + vr] = v.w;
            }
        }
        asm volatile("cp.async.wait_group 0;" ::: "memory");
        __syncthreads();               // K, V (and Q on iter 0) ready

        // ---- S = Q K^T (Q fragments reloaded from smem each ks) ----
        float s_[8][4];
#pragma unroll
        for (int j = 0; j < 8; j++)
#pragma unroll
            for (int k = 0; k < 4; k++) s_[j][k] = 0.f;

#pragma unroll
        for (int ks = 0; ks < 8; ks++) {
            uint32_t a[4];
            const int k0 = ks * 8 + q;
            a[0] = __float_as_uint(Qs[(w16 + g) * PADK + k0]);
            a[1] = __float_as_uint(Qs[(w16 + g + 8) * PADK + k0]);
            a[2] = __float_as_uint(Qs[(w16 + g) * PADK + k0 + 4]);
            a[3] = __float_as_uint(Qs[(w16 + g + 8) * PADK + k0 + 4]);
#pragma unroll
            for (int j = 0; j < 8; j++) {
                const uint32_t b0 = __float_as_uint(Ks[(j * 8 + g) * PADK + k0]);
                const uint32_t b1 = __float_as_uint(Ks[(j * 8 + g) * PADK + k0 + 4]);
                mma_tf32_b(s_[j], a, b0, b1);
            }
        }

        // ---- scale (post-MMA, exact) + causal mask ----
        if (kt >= 2 * qt) {
            const int kb = kt * 64;
            const int r0 = qt * 128 + w16 + g, r1 = r0 + 8;
#pragma unroll
            for (int j = 0; j < 8; j++) {
                const int k0 = kb + j * 8 + 2 * q;
                s_[j][0] = (k0 > r0)     ? -1e30f : s_[j][0] * 0.125f;
                s_[j][1] = (k0 + 1 > r0) ? -1e30f : s_[j][1] * 0.125f;
                s_[j][2] = (k0 > r1)     ? -1e30f : s_[j][2] * 0.125f;
                s_[j][3] = (k0 + 1 > r1) ? -1e30f : s_[j][3] * 0.125f;
            }
        } else {
#pragma unroll
            for (int j = 0; j < 8; j++) {
                s_[j][0] *= 0.125f; s_[j][1] *= 0.125f;
                s_[j][2] *= 0.125f; s_[j][3] *= 0.125f;
            }
        }

        // ---- online softmax ----
        float mx0 = -1e30f, mx1 = -1e30f;
#pragma unroll
        for (int j = 0; j < 8; j++) {
            mx0 = fmaxf(mx0, fmaxf(s_[j][0], s_[j][1]));
            mx1 = fmaxf(mx1, fmaxf(s_[j][2], s_[j][3]));
        }
        mx0 = fmaxf(mx0, __shfl_xor_sync(0xffffffffu, mx0, 1));
        mx0 = fmaxf(mx0, __shfl_xor_sync(0xffffffffu, mx0, 2));
        mx1 = fmaxf(mx1, __shfl_xor_sync(0xffffffffu, mx1, 1));
        mx1 = fmaxf(mx1, __shfl_xor_sync(0xffffffffu, mx1, 2));

        const float mn0 = fmaxf(m0, mx0), mn1 = fmaxf(m1, mx1);
        const float ex0 = __expf(m0 - mn0), ex1 = __expf(m1 - mn1);
        float rs0 = 0.f, rs1 = 0.f;
#pragma unroll
        for (int j = 0; j < 8; j++) {
            s_[j][0] = rna_tf32(__expf(s_[j][0] - mn0));
            s_[j][1] = rna_tf32(__expf(s_[j][1] - mn0));
            s_[j][2] = rna_tf32(__expf(s_[j][2] - mn1));
            s_[j][3] = rna_tf32(__expf(s_[j][3] - mn1));
            rs0 += s_[j][0] + s_[j][1];
            rs1 += s_[j][2] + s_[j][3];
        }
        rs0 += __shfl_xor_sync(0xffffffffu, rs0, 1);
        rs0 += __shfl_xor_sync(0xffffffffu, rs0, 2);
        rs1 += __shfl_xor_sync(0xffffffffu, rs1, 1);
        rs1 += __shfl_xor_sync(0xffffffffu, rs1, 2);
        l0 = l0 * ex0 + rs0;  m0 = mn0;
        l1 = l1 * ex1 + rs1;  m1 = mn1;
#pragma unroll
        for (int j = 0; j < 8; j++) {
            o_[j][0] *= ex0; o_[j][1] *= ex0;
            o_[j][2] *= ex1; o_[j][3] *= ex1;
        }

        // ---- P -> smem (per-warp rows only) ----
#pragma unroll
        for (int j = 0; j < 8; j++) {
            *(float2*)&Ps[(w16 + g) * PADK + j * 8 + 2 * q] =
                make_float2(s_[j][0], s_[j][1]);
            *(float2*)&Ps[(w16 + g + 8) * PADK + j * 8 + 2 * q] =
                make_float2(s_[j][2], s_[j][3]);
        }
        __syncwarp();

        // ---- O += P V ----
#pragma unroll
        for (int ks = 0; ks < 8; ks++) {
            uint32_t a[4];
            const int k0 = ks * 8 + q;
            a[0] = __float_as_uint(Ps[(w16 + g) * PADK + k0]);
            a[1] = __float_as_uint(Ps[(w16 + g + 8) * PADK + k0]);
            a[2] = __float_as_uint(Ps[(w16 + g) * PADK + k0 + 4]);
            a[3] = __float_as_uint(Ps[(w16 + g + 8) * PADK + k0 + 4]);
#pragma unroll
            for (int j = 0; j < 8; j++) {
                const uint32_t b0 = __float_as_uint(Vt[(j * 8 + g) * PADK + k0]);
                const uint32_t b1 = __float_as_uint(Vt[(j * 8 + g) * PADK + k0 + 4]);
                mma_tf32_b(o_[j], a, b0, b1);
            }
        }
    }

    // ---- epilogue ----
    const int b = bh >> 4, h = bh & 15;
    const float inv0 = 1.f / l0, inv1 = 1.f / l1;
    const int t0 = qt * 128 + w16 + g;
    float* dst0 = g_o + ((size_t)(b * T_ + t0)) * D_ + h * 64;
    float* dst1 = g_o + ((size_t)(b * T_ + t0 + 8)) * D_ + h * 64;
#pragma unroll
    for (int j = 0; j < 8; j++) {
        *(float2*)(dst0 + j * 8 + 2 * q) =
            make_float2(rna_tf32(o_[j][0] * inv0), rna_tf32(o_[j][1] * inv0));
        *(float2*)(dst1 + j * 8 + 2 * q) =
            make_float2(rna_tf32(o_[j][2] * inv1), rna_tf32(o_[j][3] * inv1));
    }
}

// ---------------------------------------------------------------------------
// Launch
// ---------------------------------------------------------------------------
extern "C" void kernel_launch(void* const* d_in, const int* in_sizes, int n_in,
                              void* d_out, int out_size) {
    const float* x  = (const float*)d_in[0];
    const float* Wk = (const float*)d_in[1];
    const float* Wq = (const float*)d_in[2];
    const float* Wv = (const float*)d_in[3];
    const float* Wp = (const float*)d_in[4];
    const float* bp = (const float*)d_in[5];
    float* out = (float*)d_out;

    float *qp, *kp, *vp, *op, *xr, *wr;
    cudaGetSymbolAddress((void**)&qp, g_q);
    cudaGetSymbolAddress((void**)&kp, g_k);
    cudaGetSymbolAddress((void**)&vp, g_v);
    cudaGetSymbolAddress((void**)&op, g_o);
    cudaGetSymbolAddress((void**)&xr, g_xr);
    cudaGetSymbolAddress((void**)&wr, g_wr);

    cudaFuncSetAttribute(gemm_qkv, cudaFuncAttributeMaxDynamicSharedMemorySize, GSMEM);
    cudaFuncSetAttribute(gemm_out, cudaFuncAttributeMaxDynamicSharedMemorySize, GSMEM);
    cudaFuncSetAttribute(flash_mma, cudaFuncAttributeMaxDynamicSharedMemorySize, FL_SMEM);

    const int NX = B_ * T_ * D_;
    const int NW = D_ * D_;

    // rounding
    round_tf32<<<NX / 1024, 256>>>(x, xr);
    WPtrs ws; ws.w[0] = Wk; ws.w[1] = Wq; ws.w[2] = Wv; ws.w[3] = Wp;
    round_w4<<<dim3(NW / 1024, 4), 256>>>(ws, wr);

    // fused QKV projections
    gemm_qkv<<<dim3(D_ / 128, M_ / 128, 3), 128, GSMEM>>>(xr, wr, kp, qp, vp);

    // flash attention (2 CTAs/SM)
    flash_mma<<<dim3(T_ / 128, B_ * H_), 256, FL_SMEM>>>();

    // output projection
    gemm_out<<<dim3(D_ / 128, M_ / 128), 128, GSMEM>>>(op, wr + 3 * (size_t)NW, out, bp);
}

// round 10
// speedup vs baseline: 1.0675x; 1.0675x over previous
#include <cuda_runtime.h>
#include <cstdint>

// Problem constants
#define B_  4
#define T_  2048
#define D_  1024
#define H_  16
#define HD_ 64
#define M_  (B_*T_)   // 8192

// Scratch buffers
__device__ float g_q[(size_t)B_*H_*T_*HD_];
__device__ float g_k[(size_t)B_*H_*T_*HD_];
__device__ float g_v[(size_t)B_*H_*T_*HD_];
__device__ float g_o[(size_t)B_*T_*D_];
__device__ float g_xr[(size_t)B_*T_*D_];     // tf32-rounded activations
__device__ float g_wr[(size_t)4*D_*D_];      // tf32-rounded weights (k,q,v,p)

// ---------------------------------------------------------------------------
// helpers
// ---------------------------------------------------------------------------
__device__ __forceinline__ uint32_t smem_u32(const void* p) {
    uint32_t a;
    asm("{ .reg .u64 t; cvta.to.shared.u64 t, %1; cvt.u32.u64 %0, t; }"
        : "=r"(a) : "l"(p));
    return a;
}

__device__ __forceinline__ void cp_async16(uint32_t dst, const void* src) {
    asm volatile("cp.async.cg.shared.global [%0], [%1], 16;" :: "r"(dst), "l"(src));
}

__device__ __forceinline__ void mma_tf32(float* c, const uint32_t* a, const uint32_t* b) {
    asm volatile(
        "mma.sync.aligned.m16n8k8.row.col.f32.tf32.tf32.f32 "
        "{%0,%1,%2,%3}, {%4,%5,%6,%7}, {%8,%9}, {%0,%1,%2,%3};"
        : "+f"(c[0]), "+f"(c[1]), "+f"(c[2]), "+f"(c[3])
        : "r"(a[0]), "r"(a[1]), "r"(a[2]), "r"(a[3]), "r"(b[0]), "r"(b[1]));
}

__device__ __forceinline__ void mma_tf32_b(float* c, const uint32_t* a,
                                           uint32_t b0, uint32_t b1) {
    asm volatile(
        "mma.sync.aligned.m16n8k8.row.col.f32.tf32.tf32.f32 "
        "{%0,%1,%2,%3}, {%4,%5,%6,%7}, {%8,%9}, {%0,%1,%2,%3};"
        : "+f"(c[0]), "+f"(c[1]), "+f"(c[2]), "+f"(c[3])
        : "r"(a[0]), "r"(a[1]), "r"(a[2]), "r"(a[3]), "r"(b0), "r"(b1));
}

__device__ __forceinline__ float rna_tf32(float x) {
    uint32_t u;
    asm("cvt.rna.tf32.f32 %0, %1;" : "=r"(u) : "f"(x));
    return __uint_as_float(u);
}

// ---------------------------------------------------------------------------
// tf32 pre-rounding
// ---------------------------------------------------------------------------
__global__ void __launch_bounds__(256) round_tf32(const float* __restrict__ x,
                                                  float* __restrict__ y) {
    const size_t i = ((size_t)blockIdx.x * 256 + threadIdx.x) * 4;
    float4 v = *(const float4*)(x + i);
    float4 o;
    o.x = rna_tf32(v.x); o.y = rna_tf32(v.y);
    o.z = rna_tf32(v.z); o.w = rna_tf32(v.w);
    *(float4*)(y + i) = o;
}

struct WPtrs { const float* w[4]; };
__global__ void __launch_bounds__(256) round_w4(WPtrs ws, float* __restrict__ y) {
    const int z = blockIdx.y;
    const float* src = ws.w[z];
    float* dst = y + (size_t)z * D_ * D_;
    const size_t i = ((size_t)blockIdx.x * 256 + threadIdx.x) * 4;
    float4 v = *(const float4*)(src + i);
    float4 o;
    o.x = rna_tf32(v.x); o.y = rna_tf32(v.y);
    o.z = rna_tf32(v.z); o.w = rna_tf32(v.w);
    *(float4*)(dst + i) = o;
}

// ---------------------------------------------------------------------------
// GEMM (unchanged — known good)
// ---------------------------------------------------------------------------
#define SROW   36
#define STG_F  (128 * SROW)
#define STAGE_F (2 * STG_F)
#define GSMEM  (3 * STAGE_F * 4)   // 110592 B

template<int MODE>
__device__ __forceinline__ void gemm_body(const float* __restrict__ A,
                                          const float* __restrict__ W,
                                          float* __restrict__ out,
                                          const float* __restrict__ bias,
                                          float* sm, int bx, int by) {
    const int tid  = threadIdx.x;
    const int lane = tid & 31;
    const int wid  = tid >> 5;
    const int wm   = wid >> 1;
    const int wn   = wid & 1;

    float c[4][8][4];
#pragma unroll
    for (int i = 0; i < 4; i++)
#pragma unroll
        for (int j = 0; j < 8; j++)
#pragma unroll
            for (int k = 0; k < 4; k++) c[i][j][k] = 0.f;

    const int lr = tid >> 3;
    const int ls = tid & 7;
    const float* Ag = A + (size_t)(by * 128 + lr) * 1024 + ls * 4;
    const float* Wg = W + (size_t)(bx * 128 + lr) * 1024 + ls * 4;

    const uint32_t ldst = smem_u32(sm) + (lr * SROW + ls * 4) * 4;

    auto load_tile = [&](int kt, int s) {
        const uint32_t aB = ldst + (uint32_t)s * (STAGE_F * 4);
        const uint32_t bB = aB + STG_F * 4;
        const float* Ak = Ag + kt * 32;
        const float* Wk = Wg + kt * 32;
#pragma unroll
        for (int i = 0; i < 8; i++) {
            cp_async16(aB + i * 16 * (SROW * 4), Ak + (size_t)i * 16 * 1024);
            cp_async16(bB + i * 16 * (SROW * 4), Wk + (size_t)i * 16 * 1024);
        }
        asm volatile("cp.async.commit_group;" ::: "memory");
    };

    load_tile(0, 0);
    load_tile(1, 1);

    const int g = lane >> 2;
    const int q = lane & 3;

    uint32_t af[2][4][4], bf[2][8][2];

    auto frag_load = [&](const uint32_t* As, const uint32_t* Bs, int ks, int buf) {
        const int k0 = ks * 8 + q;
#pragma unroll
        for (int mm = 0; mm < 4; mm++) {
            af[buf][mm][0] = As[(mm * 16)     * SROW + k0];
            af[buf][mm][1] = As[(mm * 16 + 8) * SROW + k0];
            af[buf][mm][2] = As[(mm * 16)     * SROW + k0 + 4];
            af[buf][mm][3] = As[(mm * 16 + 8) * SROW + k0 + 4];
        }
#pragma unroll
        for (int nn = 0; nn < 8; nn++) {
            bf[buf][nn][0] = Bs[(nn * 8) * SROW + k0];
            bf[buf][nn][1] = Bs[(nn * 8) * SROW + k0 + 4];
        }
    };

    int s = 0, sl = 2;
    for (int kt = 0; kt < 32; kt++) {
        if (kt < 31) {
            asm volatile("cp.async.wait_group 1;" ::: "memory");
        } else {
            asm volatile("cp.async.wait_group 0;" ::: "memory");
        }
        __syncthreads();

        if (kt + 2 < 32) {
            load_tile(kt + 2, sl);
            sl = (sl == 2) ? 0 : sl + 1;
        }

        const uint32_t* As = (const uint32_t*)(sm + s * STAGE_F) +
                             (wm * 64 + g) * SROW;
        const uint32_t* Bs = (const uint32_t*)(sm + s * STAGE_F + STG_F) +
                             (wn * 64 + g) * SROW;

        frag_load(As, Bs, 0, 0);
#pragma unroll
        for (int ks = 0; ks < 4; ks++) {
            const int cur = ks & 1;
            if (ks < 3) frag_load(As, Bs, ks + 1, cur ^ 1);
#pragma unroll
            for (int mm = 0; mm < 4; mm++)
#pragma unroll
                for (int nn = 0; nn < 8; nn++)
                    mma_tf32(c[mm][nn], af[cur][mm], bf[cur][nn]);
        }
        s = (s == 2) ? 0 : s + 1;
    }

    const int rbase = by * 128 + wm * 64 + g;
    const int cbase = bx * 128 + wn * 64 + 2 * q;
#pragma unroll
    for (int mm = 0; mm < 4; mm++) {
        const int r0 = rbase + mm * 16;
#pragma unroll
        for (int nn = 0; nn < 8; nn++) {
            const int cc = cbase + nn * 8;
            if (MODE == 0) {
                const int h = cc >> 6, d = cc & 63;
                const int b = r0 >> 11, t = r0 & 2047;
                float* dst = out + (((size_t)(b * H_ + h)) * T_ + t) * HD_ + d;
                *(float2*)dst =
                    make_float2(rna_tf32(c[mm][nn][0]), rna_tf32(c[mm][nn][1]));
                *(float2*)(dst + 8 * HD_) =
                    make_float2(rna_tf32(c[mm][nn][2]), rna_tf32(c[mm][nn][3]));
            } else {
                float2 bb = *(const float2*)(bias + cc);
                float* dst = out + (size_t)r0 * 1024 + cc;
                *(float2*)dst = make_float2(c[mm][nn][0] + bb.x, c[mm][nn][1] + bb.y);
                *(float2*)(dst + 8 * 1024) =
                    make_float2(c[mm][nn][2] + bb.x, c[mm][nn][3] + bb.y);
            }
        }
    }
}

__global__ void __launch_bounds__(128) gemm_qkv(const float* __restrict__ A,
                                                const float* __restrict__ Wr,
                                                float* __restrict__ o0,
                                                float* __restrict__ o1,
                                                float* __restrict__ o2) {
    extern __shared__ float sm[];
    const int z = blockIdx.z;
    const float* W = Wr + (size_t)z * D_ * D_;
    float* out = (z == 0) ? o0 : (z == 1) ? o1 : o2;
    gemm_body<0>(A, W, out, nullptr, sm, blockIdx.x, blockIdx.y);
}

__global__ void __launch_bounds__(128) gemm_out(const float* __restrict__ A,
                                                const float* __restrict__ W,
                                                float* __restrict__ out,
                                                const float* __restrict__ bias) {
    extern __shared__ float sm[];
    gemm_body<1>(A, W, out, bias, sm, blockIdx.x, blockIdx.y);
}

// ---------------------------------------------------------------------------
// Flash attention v3: Q-in-regs + double-buffered K (cp.async) + V via
// cp.async staging + smem transpose, 2 CTAs/SM.
// smem: Ks[2][64*68] + Vn[64*68] + Vt[64*68] + Ps[128*68] = 104448 B.
// Per tile: 2 barriers; K(t+1) prefetch and V(t) arrival overlap the S-MMAs.
// ---------------------------------------------------------------------------
#define PADK 68
#define KS_F (64 * PADK)
#define FL_SMEM ((2 * KS_F + KS_F + KS_F + 128 * PADK) * 4)   // 104448

__global__ void __launch_bounds__(256, 2) flash_mma() {
    extern __shared__ float sm[];
    float* Ks = sm;                        // [2][64][PADK] keys (double buffer)
    float* Vn = sm + 2 * KS_F;             // [64][PADK] V natural (staging)
    float* Vt = sm + 3 * KS_F;             // [64][PADK] V transposed (d, key)
    float* Ps = sm + 4 * KS_F;             // [128][PADK] Q staging, then P

    const int tid = threadIdx.x, lane = tid & 31, wid = tid >> 5;
    const int g = lane >> 2, q = lane & 3;
    const int qt = blockIdx.x, bh = blockIdx.y;
    const int w16 = wid * 16;

    const float* Qg = g_q + (size_t)bh * T_ * HD_ + (size_t)qt * 128 * HD_;
    const float* Kg = g_k + (size_t)bh * T_ * HD_;
    const float* Vg = g_v + (size_t)bh * T_ * HD_;

    const uint32_t sb  = smem_u32(sm);
    const uint32_t VnB = sb + 2 * KS_F * 4;
    const uint32_t PsB = sb + 4 * KS_F * 4;

    // ---- prologue: Q -> Ps and K(0) -> Ks[0], one cp.async group ----
    {
        const int row = tid >> 1, segb = (tid & 1) * 8;
#pragma unroll
        for (int i = 0; i < 8; i++)
            cp_async16(PsB + (row * PADK + (segb + i) * 4) * 4,
                       Qg + row * 64 + (segb + i) * 4);
#pragma unroll
        for (int i = 0; i < 4; i++) {
            const int idx = tid + i * 256;
            cp_async16(sb + ((idx >> 4) * PADK + (idx & 15) * 4) * 4,
                       Kg + (idx >> 4) * 64 + (idx & 15) * 4);
        }
        asm volatile("cp.async.commit_group;" ::: "memory");
        asm volatile("cp.async.wait_group 0;" ::: "memory");
        __syncthreads();
    }

    // Q fragments to registers, pre-scaled by 1/sqrt(hd) (exact)
    uint32_t qf[8][4];
#pragma unroll
    for (int ks = 0; ks < 8; ks++) {
        qf[ks][0] = __float_as_uint(Ps[(w16 + g) * PADK + ks * 8 + q] * 0.125f);
        qf[ks][1] = __float_as_uint(Ps[(w16 + g + 8) * PADK + ks * 8 + q] * 0.125f);
        qf[ks][2] = __float_as_uint(Ps[(w16 + g) * PADK + ks * 8 + q + 4] * 0.125f);
        qf[ks][3] = __float_as_uint(Ps[(w16 + g + 8) * PADK + ks * 8 + q + 4] * 0.125f);
    }
    __syncthreads();   // Ps free for P

    float o_[8][4];
#pragma unroll
    for (int j = 0; j < 8; j++)
#pragma unroll
        for (int k = 0; k < 4; k++) o_[j][k] = 0.f;
    float m0 = -1e30f, m1 = -1e30f, l0 = 0.f, l1 = 0.f;

    const int vr = tid & 63, vqr = tid >> 6;   // V transpose mapping
    const int nkt = 2 * qt + 2;

    for (int kt = 0; kt < nkt; kt++) {
        const int s = kt & 1;
        const bool has_next = (kt + 1 < nkt);

        if (kt > 0) {
            asm volatile("cp.async.wait_group 0;" ::: "memory");  // K(kt) arrived
            __syncthreads();   // K visible; prior PV reads of Vt/Ks done
        }

        // V(kt) -> Vn staging (group 1)
        {
            const float* Vk = Vg + (size_t)kt * 64 * 64;
#pragma unroll
            for (int i = 0; i < 4; i++) {
                const int idx = tid + i * 256;
                cp_async16(VnB + ((idx >> 4) * PADK + (idx & 15) * 4) * 4,
                           Vk + (idx >> 4) * 64 + (idx & 15) * 4);
            }
            asm volatile("cp.async.commit_group;" ::: "memory");
        }
        // K(kt+1) prefetch (group 2)
        if (has_next) {
            const float* Kn = Kg + (size_t)(kt + 1) * 64 * 64;
            const uint32_t kb = sb + (uint32_t)(s ^ 1) * (KS_F * 4);
#pragma unroll
            for (int i = 0; i < 4; i++) {
                const int idx = tid + i * 256;
                cp_async16(kb + ((idx >> 4) * PADK + (idx & 15) * 4) * 4,
                           Kn + (idx >> 4) * 64 + (idx & 15) * 4);
            }
            asm volatile("cp.async.commit_group;" ::: "memory");
        }

        // ---- S = Q K^T (hides V arrival + K prefetch) ----
        float s_[8][4];
#pragma unroll
        for (int j = 0; j < 8; j++)
#pragma unroll
            for (int k = 0; k < 4; k++) s_[j][k] = 0.f;

        const float* Kb = Ks + s * KS_F;
#pragma unroll
        for (int ks = 0; ks < 8; ks++) {
#pragma unroll
            for (int j = 0; j < 8; j++) {
                const uint32_t b0 = __float_as_uint(Kb[(j * 8 + g) * PADK + ks * 8 + q]);
                const uint32_t b1 = __float_as_uint(Kb[(j * 8 + g) * PADK + ks * 8 + q + 4]);
                mma_tf32_b(s_[j], qf[ks], b0, b1);
            }
        }

        // ---- V: wait staging, transpose Vn -> Vt ----
        if (has_next) {
            asm volatile("cp.async.wait_group 1;" ::: "memory");  // V done, K may fly
        } else {
            asm volatile("cp.async.wait_group 0;" ::: "memory");
        }
#pragma unroll
        for (int i = 0; i < 4; i++) {
            const int d = vqr * 16 + i * 4;
            float4 v = *(const float4*)&Vn[vr * PADK + d];
            Vt[(d + 0) * PADK + vr] = v.x;
            Vt[(d + 1) * PADK + vr] = v.y;
            Vt[(d + 2) * PADK + vr] = v.z;
            Vt[(d + 3) * PADK + vr] = v.w;
        }

        // ---- causal mask (pre-scaled S; last two tiles only) ----
        if (kt >= 2 * qt) {
            const int kb2 = kt * 64;
            const int r0 = qt * 128 + w16 + g, r1 = r0 + 8;
#pragma unroll
            for (int j = 0; j < 8; j++) {
                const int k0 = kb2 + j * 8 + 2 * q;
                if (k0 > r0)     s_[j][0] = -1e30f;
                if (k0 + 1 > r0) s_[j][1] = -1e30f;
                if (k0 > r1)     s_[j][2] = -1e30f;
                if (k0 + 1 > r1) s_[j][3] = -1e30f;
            }
        }

        // ---- online softmax ----
        float mx0 = -1e30f, mx1 = -1e30f;
#pragma unroll
        for (int j = 0; j < 8; j++) {
            mx0 = fmaxf(mx0, fmaxf(s_[j][0], s_[j][1]));
            mx1 = fmaxf(mx1, fmaxf(s_[j][2], s_[j][3]));
        }
        mx0 = fmaxf(mx0, __shfl_xor_sync(0xffffffffu, mx0, 1));
        mx0 = fmaxf(mx0, __shfl_xor_sync(0xffffffffu, mx0, 2));
        mx1 = fmaxf(mx1, __shfl_xor_sync(0xffffffffu, mx1, 1));
        mx1 = fmaxf(mx1, __shfl_xor_sync(0xffffffffu, mx1, 2));

        const float mn0 = fmaxf(m0, mx0), mn1 = fmaxf(m1, mx1);
        const float ex0 = __expf(m0 - mn0), ex1 = __expf(m1 - mn1);
        float rs0 = 0.f, rs1 = 0.f;
#pragma unroll
        for (int j = 0; j < 8; j++) {
            s_[j][0] = rna_tf32(__expf(s_[j][0] - mn0));
            s_[j][1] = rna_tf32(__expf(s_[j][1] - mn0));
            s_[j][2] = rna_tf32(__expf(s_[j][2] - mn1));
            s_[j][3] = rna_tf32(__expf(s_[j][3] - mn1));
            rs0 += s_[j][0] + s_[j][1];
            rs1 += s_[j][2] + s_[j][3];
        }
        rs0 += __shfl_xor_sync(0xffffffffu, rs0, 1);
        rs0 += __shfl_xor_sync(0xffffffffu, rs0, 2);
        rs1 += __shfl_xor_sync(0xffffffffu, rs1, 1);
        rs1 += __shfl_xor_sync(0xffffffffu, rs1, 2);
        l0 = l0 * ex0 + rs0;  m0 = mn0;
        l1 = l1 * ex1 + rs1;  m1 = mn1;
#pragma unroll
        for (int j = 0; j < 8; j++) {
            o_[j][0] *= ex0; o_[j][1] *= ex0;
            o_[j][2] *= ex1; o_[j][3] *= ex1;
        }

        // ---- P -> smem (per-warp rows) ----
#pragma unroll
        for (int j = 0; j < 8; j++) {
            *(float2*)&Ps[(w16 + g) * PADK + j * 8 + 2 * q] =
                make_float2(s_[j][0], s_[j][1]);
            *(float2*)&Ps[(w16 + g + 8) * PADK + j * 8 + 2 * q] =
                make_float2(s_[j][2], s_[j][3]);
        }
        __syncthreads();   // Vt (all warps) + P ready

        // ---- O += P V ----
#pragma unroll
        for (int ks = 0; ks < 8; ks++) {
            uint32_t a[4];
            const int k0 = ks * 8 + q;
            a[0] = __float_as_uint(Ps[(w16 + g) * PADK + k0]);
            a[1] = __float_as_uint(Ps[(w16 + g + 8) * PADK + k0]);
            a[2] = __float_as_uint(Ps[(w16 + g) * PADK + k0 + 4]);
            a[3] = __float_as_uint(Ps[(w16 + g + 8) * PADK + k0 + 4]);
#pragma unroll
            for (int j = 0; j < 8; j++) {
                const uint32_t b0 = __float_as_uint(Vt[(j * 8 + g) * PADK + k0]);
                const uint32_t b1 = __float_as_uint(Vt[(j * 8 + g) * PADK + k0 + 4]);
                mma_tf32_b(o_[j], a, b0, b1);
            }
        }
    }

    // ---- epilogue ----
    const int b = bh >> 4, h = bh & 15;
    const float inv0 = 1.f / l0, inv1 = 1.f / l1;
    const int t0 = qt * 128 + w16 + g;
    float* dst0 = g_o + ((size_t)(b * T_ + t0)) * D_ + h * 64;
    float* dst1 = g_o + ((size_t)(b * T_ + t0 + 8)) * D_ + h * 64;
#pragma unroll
    for (int j = 0; j < 8; j++) {
        *(float2*)(dst0 + j * 8 + 2 * q) =
            make_float2(rna_tf32(o_[j][0] * inv0), rna_tf32(o_[j][1] * inv0));
        *(float2*)(dst1 + j * 8 + 2 * q) =
            make_float2(rna_tf32(o_[j][2] * inv1), rna_tf32(o_[j][3] * inv1));
    }
}

// ---------------------------------------------------------------------------
// Launch
// ---------------------------------------------------------------------------
extern "C" void kernel_launch(void* const* d_in, const int* in_sizes, int n_in,
                              void* d_out, int out_size) {
    const float* x  = (const float*)d_in[0];
    const float* Wk = (const float*)d_in[1];
    const float* Wq = (const float*)d_in[2];
    const float* Wv = (const float*)d_in[3];
    const float* Wp = (const float*)d_in[4];
    const float* bp = (const float*)d_in[5];
    float* out = (float*)d_out;

    float *qp, *kp, *vp, *op, *xr, *wr;
    cudaGetSymbolAddress((void**)&qp, g_q);
    cudaGetSymbolAddress((void**)&kp, g_k);
    cudaGetSymbolAddress((void**)&vp, g_v);
    cudaGetSymbolAddress((void**)&op, g_o);
    cudaGetSymbolAddress((void**)&xr, g_xr);
    cudaGetSymbolAddress((void**)&wr, g_wr);

    cudaFuncSetAttribute(gemm_qkv, cudaFuncAttributeMaxDynamicSharedMemorySize, GSMEM);
    cudaFuncSetAttribute(gemm_out, cudaFuncAttributeMaxDynamicSharedMemorySize, GSMEM);
    cudaFuncSetAttribute(flash_mma, cudaFuncAttributeMaxDynamicSharedMemorySize, FL_SMEM);

    const int NX = B_ * T_ * D_;
    const int NW = D_ * D_;

    // rounding
    round_tf32<<<NX / 1024, 256>>>(x, xr);
    WPtrs ws; ws.w[0] = Wk; ws.w[1] = Wq; ws.w[2] = Wv; ws.w[3] = Wp;
    round_w4<<<dim3(NW / 1024, 4), 256>>>(ws, wr);

    // fused QKV projections
    gemm_qkv<<<dim3(D_ / 128, M_ / 128, 3), 128, GSMEM>>>(xr, wr, kp, qp, vp);

    // flash attention v3
    flash_mma<<<dim3(T_ / 128, B_ * H_), 256, FL_SMEM>>>();

    // output projection
    gemm_out<<<dim3(D_ / 128, M_ / 128), 128, GSMEM>>>(op, wr + 3 * (size_t)NW, out, bp);
}

// round 13
// speedup vs baseline: 1.1268x; 1.0555x over previous
#include <cuda_runtime.h>
#include <cstdint>

// Problem constants
#define B_  4
#define T_  2048
#define D_  1024
#define H_  16
#define HD_ 64
#define M_  (B_*T_)   // 8192

// Scratch buffers
__device__ float g_q[(size_t)B_*H_*T_*HD_];
__device__ float g_k[(size_t)B_*H_*T_*HD_];
__device__ float g_v[(size_t)B_*H_*T_*HD_];
__device__ float g_o[(size_t)B_*T_*D_];
__device__ float g_xr[(size_t)B_*T_*D_];     // tf32-rounded activations
__device__ float g_wr[(size_t)4*D_*D_];      // tf32-rounded weights (k,q,v,p)

// ---------------------------------------------------------------------------
// helpers
// ---------------------------------------------------------------------------
__device__ __forceinline__ uint32_t smem_u32(const void* p) {
    uint32_t a;
    asm("{ .reg .u64 t; cvta.to.shared.u64 t, %1; cvt.u32.u64 %0, t; }"
        : "=r"(a) : "l"(p));
    return a;
}

__device__ __forceinline__ void cp_async16(uint32_t dst, const void* src) {
    asm volatile("cp.async.cg.shared.global [%0], [%1], 16;" :: "r"(dst), "l"(src));
}

__device__ __forceinline__ void mma_tf32(float* c, const uint32_t* a, const uint32_t* b) {
    asm volatile(
        "mma.sync.aligned.m16n8k8.row.col.f32.tf32.tf32.f32 "
        "{%0,%1,%2,%3}, {%4,%5,%6,%7}, {%8,%9}, {%0,%1,%2,%3};"
        : "+f"(c[0]), "+f"(c[1]), "+f"(c[2]), "+f"(c[3])
        : "r"(a[0]), "r"(a[1]), "r"(a[2]), "r"(a[3]), "r"(b[0]), "r"(b[1]));
}

__device__ __forceinline__ void mma_tf32_b(float* c, const uint32_t* a,
                                           uint32_t b0, uint32_t b1) {
    asm volatile(
        "mma.sync.aligned.m16n8k8.row.col.f32.tf32.tf32.f32 "
        "{%0,%1,%2,%3}, {%4,%5,%6,%7}, {%8,%9}, {%0,%1,%2,%3};"
        : "+f"(c[0]), "+f"(c[1]), "+f"(c[2]), "+f"(c[3])
        : "r"(a[0]), "r"(a[1]), "r"(a[2]), "r"(a[3]), "r"(b0), "r"(b1));
}

__device__ __forceinline__ float rna_tf32(float x) {
    uint32_t u;
    asm("cvt.rna.tf32.f32 %0, %1;" : "=r"(u) : "f"(x));
    return __uint_as_float(u);
}

// ---------------------------------------------------------------------------
// tf32 pre-rounding
// ---------------------------------------------------------------------------
__global__ void __launch_bounds__(256) round_tf32(const float* __restrict__ x,
                                                  float* __restrict__ y) {
    const size_t i = ((size_t)blockIdx.x * 256 + threadIdx.x) * 4;
    float4 v = *(const float4*)(x + i);
    float4 o;
    o.x = rna_tf32(v.x); o.y = rna_tf32(v.y);
    o.z = rna_tf32(v.z); o.w = rna_tf32(v.w);
    *(float4*)(y + i) = o;
}

struct WPtrs { const float* w[4]; };
__global__ void __launch_bounds__(256) round_w4(WPtrs ws, float* __restrict__ y) {
    const int z = blockIdx.y;
    const float* src = ws.w[z];
    float* dst = y + (size_t)z * D_ * D_;
    const size_t i = ((size_t)blockIdx.x * 256 + threadIdx.x) * 4;
    float4 v = *(const float4*)(src + i);
    float4 o;
    o.x = rna_tf32(v.x); o.y = rna_tf32(v.y);
    o.z = rna_tf32(v.z); o.w = rna_tf32(v.w);
    *(float4*)(dst + i) = o;
}

// ---------------------------------------------------------------------------
// GEMM (unchanged — known good)
// ---------------------------------------------------------------------------
#define SROW   36
#define STG_F  (128 * SROW)
#define STAGE_F (2 * STG_F)
#define GSMEM  (3 * STAGE_F * 4)   // 110592 B

template<int MODE>
__device__ __forceinline__ void gemm_body(const float* __restrict__ A,
                                          const float* __restrict__ W,
                                          float* __restrict__ out,
                                          const float* __restrict__ bias,
                                          float* sm, int bx, int by) {
    const int tid  = threadIdx.x;
    const int lane = tid & 31;
    const int wid  = tid >> 5;
    const int wm   = wid >> 1;
    const int wn   = wid & 1;

    float c[4][8][4];
#pragma unroll
    for (int i = 0; i < 4; i++)
#pragma unroll
        for (int j = 0; j < 8; j++)
#pragma unroll
            for (int k = 0; k < 4; k++) c[i][j][k] = 0.f;

    const int lr = tid >> 3;
    const int ls = tid & 7;
    const float* Ag = A + (size_t)(by * 128 + lr) * 1024 + ls * 4;
    const float* Wg = W + (size_t)(bx * 128 + lr) * 1024 + ls * 4;

    const uint32_t ldst = smem_u32(sm) + (lr * SROW + ls * 4) * 4;

    auto load_tile = [&](int kt, int s) {
        const uint32_t aB = ldst + (uint32_t)s * (STAGE_F * 4);
        const uint32_t bB = aB + STG_F * 4;
        const float* Ak = Ag + kt * 32;
        const float* Wk = Wg + kt * 32;
#pragma unroll
        for (int i = 0; i < 8; i++) {
            cp_async16(aB + i * 16 * (SROW * 4), Ak + (size_t)i * 16 * 1024);
            cp_async16(bB + i * 16 * (SROW * 4), Wk + (size_t)i * 16 * 1024);
        }
        asm volatile("cp.async.commit_group;" ::: "memory");
    };

    load_tile(0, 0);
    load_tile(1, 1);

    const int g = lane >> 2;
    const int q = lane & 3;

    uint32_t af[2][4][4], bf[2][8][2];

    auto frag_load = [&](const uint32_t* As, const uint32_t* Bs, int ks, int buf) {
        const int k0 = ks * 8 + q;
#pragma unroll
        for (int mm = 0; mm < 4; mm++) {
            af[buf][mm][0] = As[(mm * 16)     * SROW + k0];
            af[buf][mm][1] = As[(mm * 16 + 8) * SROW + k0];
            af[buf][mm][2] = As[(mm * 16)     * SROW + k0 + 4];
            af[buf][mm][3] = As[(mm * 16 + 8) * SROW + k0 + 4];
        }
#pragma unroll
        for (int nn = 0; nn < 8; nn++) {
            bf[buf][nn][0] = Bs[(nn * 8) * SROW + k0];
            bf[buf][nn][1] = Bs[(nn * 8) * SROW + k0 + 4];
        }
    };

    int s = 0, sl = 2;
    for (int kt = 0; kt < 32; kt++) {
        if (kt < 31) {
            asm volatile("cp.async.wait_group 1;" ::: "memory");
        } else {
            asm volatile("cp.async.wait_group 0;" ::: "memory");
        }
        __syncthreads();

        if (kt + 2 < 32) {
            load_tile(kt + 2, sl);
            sl = (sl == 2) ? 0 : sl + 1;
        }

        const uint32_t* As = (const uint32_t*)(sm + s * STAGE_F) +
                             (wm * 64 + g) * SROW;
        const uint32_t* Bs = (const uint32_t*)(sm + s * STAGE_F + STG_F) +
                             (wn * 64 + g) * SROW;

        frag_load(As, Bs, 0, 0);
#pragma unroll
        for (int ks = 0; ks < 4; ks++) {
            const int cur = ks & 1;
            if (ks < 3) frag_load(As, Bs, ks + 1, cur ^ 1);
#pragma unroll
            for (int mm = 0; mm < 4; mm++)
#pragma unroll
                for (int nn = 0; nn < 8; nn++)
                    mma_tf32(c[mm][nn], af[cur][mm], bf[cur][nn]);
        }
        s = (s == 2) ? 0 : s + 1;
    }

    const int rbase = by * 128 + wm * 64 + g;
    const int cbase = bx * 128 + wn * 64 + 2 * q;
#pragma unroll
    for (int mm = 0; mm < 4; mm++) {
        const int r0 = rbase + mm * 16;
#pragma unroll
        for (int nn = 0; nn < 8; nn++) {
            const int cc = cbase + nn * 8;
            if (MODE == 0) {
                const int h = cc >> 6, d = cc & 63;
                const int b = r0 >> 11, t = r0 & 2047;
                float* dst = out + (((size_t)(b * H_ + h)) * T_ + t) * HD_ + d;
                *(float2*)dst =
                    make_float2(rna_tf32(c[mm][nn][0]), rna_tf32(c[mm][nn][1]));
                *(float2*)(dst + 8 * HD_) =
                    make_float2(rna_tf32(c[mm][nn][2]), rna_tf32(c[mm][nn][3]));
            } else {
                float2 bb = *(const float2*)(bias + cc);
                float* dst = out + (size_t)r0 * 1024 + cc;
                *(float2*)dst = make_float2(c[mm][nn][0] + bb.x, c[mm][nn][1] + bb.y);
                *(float2*)(dst + 8 * 1024) =
                    make_float2(c[mm][nn][2] + bb.x, c[mm][nn][3] + bb.y);
            }
        }
    }
}

__global__ void __launch_bounds__(128) gemm_qkv(const float* __restrict__ A,
                                                const float* __restrict__ Wr,
                                                float* __restrict__ o0,
                                                float* __restrict__ o1,
                                                float* __restrict__ o2) {
    extern __shared__ float sm[];
    const int z = blockIdx.z;
    const float* W = Wr + (size_t)z * D_ * D_;
    float* out = (z == 0) ? o0 : (z == 1) ? o1 : o2;
    gemm_body<0>(A, W, out, nullptr, sm, blockIdx.x, blockIdx.y);
}

__global__ void __launch_bounds__(128) gemm_out(const float* __restrict__ A,
                                                const float* __restrict__ W,
                                                float* __restrict__ out,
                                                const float* __restrict__ bias) {
    extern __shared__ float sm[];
    gemm_body<1>(A, W, out, bias, sm, blockIdx.x, blockIdx.y);
}

// ---------------------------------------------------------------------------
// Flash attention v4: NO V transpose.  V kept in natural [key][dim] layout
// with row pad 72 -> PV B-fragment reads are conflict-free scalar LDS
// (bank = 8q + g + 8j, all 32 lanes distinct).  K and V both double-buffered
// via cp.async, prefetched one tile ahead.  Q in registers (pre-scaled).
// smem: Ks[2][64*68] + Vs[2][64*72] + Ps[128*68] = 106496 B -> 2 CTAs/SM.
// ---------------------------------------------------------------------------
#define PADK 68
#define PADV 72
#define KS_F (64 * PADK)   // 4352
#define VS_F (64 * PADV)   // 4608
#define FL_SMEM ((2 * KS_F + 2 * VS_F + 128 * PADK) * 4)   // 106496

__global__ void __launch_bounds__(256, 2) flash_mma() {
    extern __shared__ float sm[];
    float* Ks = sm;                         // [2][64][PADK] keys
    float* Vs = sm + 2 * KS_F;              // [2][64][PADV] values (natural)
    float* Ps = sm + 2 * KS_F + 2 * VS_F;   // [128][PADK] Q staging, then P

    const int tid = threadIdx.x, lane = tid & 31, wid = tid >> 5;
    const int g = lane >> 2, q = lane & 3;
    const int qt = blockIdx.x, bh = blockIdx.y;
    const int w16 = wid * 16;

    const float* Qg = g_q + (size_t)bh * T_ * HD_ + (size_t)qt * 128 * HD_;
    const float* Kg = g_k + (size_t)bh * T_ * HD_;
    const float* Vg = g_v + (size_t)bh * T_ * HD_;

    const uint32_t sb  = smem_u32(sm);
    const uint32_t VsB = sb + 2 * KS_F * 4;
    const uint32_t PsB = sb + (2 * KS_F + 2 * VS_F) * 4;

    const int lrow = tid >> 4;       // 0..15 -> covers 64 rows in 4 steps
    const int lchk = tid & 15;       // 16B chunk within 64-float row

    auto load_kv = [&](int kt, int s) {
        const float* Kt = Kg + (size_t)kt * 64 * 64;
        const float* Vt = Vg + (size_t)kt * 64 * 64;
        const uint32_t kB = sb + (uint32_t)s * (KS_F * 4);
        const uint32_t vB = VsB + (uint32_t)s * (VS_F * 4);
#pragma unroll
        for (int i = 0; i < 4; i++) {
            const int r = lrow + i * 16;
            cp_async16(kB + (r * PADK + lchk * 4) * 4, Kt + r * 64 + lchk * 4);
            cp_async16(vB + (r * PADV + lchk * 4) * 4, Vt + r * 64 + lchk * 4);
        }
        asm volatile("cp.async.commit_group;" ::: "memory");
    };

    // ---- prologue: Q + K0/V0 (group 0), K1/V1 (group 1) ----
    {
        const int row = tid >> 1, segb = (tid & 1) * 8;
#pragma unroll
        for (int i = 0; i < 8; i++)
            cp_async16(PsB + (row * PADK + (segb + i) * 4) * 4,
                       Qg + row * 64 + (segb + i) * 4);
    }
    load_kv(0, 0);                       // closes group 0 (Q + K0/V0)
    const int nkt = 2 * qt + 2;
    load_kv(1, 1);                       // group 1 (nkt >= 2 always)

    asm volatile("cp.async.wait_group 1;" ::: "memory");   // group 0 done
    __syncthreads();

    // Q fragments to registers, pre-scaled by 1/sqrt(hd) (exact)
    uint32_t qf[8][4];
#pragma unroll
    for (int ks = 0; ks < 8; ks++) {
        qf[ks][0] = __float_as_uint(Ps[(w16 + g) * PADK + ks * 8 + q] * 0.125f);
        qf[ks][1] = __float_as_uint(Ps[(w16 + g + 8) * PADK + ks * 8 + q] * 0.125f);
        qf[ks][2] = __float_as_uint(Ps[(w16 + g) * PADK + ks * 8 + q + 4] * 0.125f);
        qf[ks][3] = __float_as_uint(Ps[(w16 + g + 8) * PADK + ks * 8 + q + 4] * 0.125f);
    }
    __syncthreads();   // Ps free for P

    float o_[8][4];
#pragma unroll
    for (int j = 0; j < 8; j++)
#pragma unroll
        for (int k = 0; k < 4; k++) o_[j][k] = 0.f;
    float m0 = -1e30f, m1 = -1e30f, l0 = 0.f, l1 = 0.f;

    for (int kt = 0; kt < nkt; kt++) {
        const int s = kt & 1;

        if (kt > 0) {
            asm volatile("cp.async.wait_group 1;" ::: "memory");  // K/V(kt) arrived
            __syncthreads();
        }

        // ---- S = Q K^T ----
        float s_[8][4];
#pragma unroll
        for (int j = 0; j < 8; j++)
#pragma unroll
            for (int k = 0; k < 4; k++) s_[j][k] = 0.f;

        const float* Kb = Ks + s * KS_F;
#pragma unroll
        for (int ks = 0; ks < 8; ks++) {
#pragma unroll
            for (int j = 0; j < 8; j++) {
                const uint32_t b0 = __float_as_uint(Kb[(j * 8 + g) * PADK + ks * 8 + q]);
                const uint32_t b1 = __float_as_uint(Kb[(j * 8 + g) * PADK + ks * 8 + q + 4]);
                mma_tf32_b(s_[j], qf[ks], b0, b1);
            }
        }

        // ---- causal mask (last two tiles only; S pre-scaled via Q) ----
        if (kt >= 2 * qt) {
            const int kb2 = kt * 64;
            const int r0 = qt * 128 + w16 + g, r1 = r0 + 8;
#pragma unroll
            for (int j = 0; j < 8; j++) {
                const int k0 = kb2 + j * 8 + 2 * q;
                if (k0 > r0)     s_[j][0] = -1e30f;
                if (k0 + 1 > r0) s_[j][1] = -1e30f;
                if (k0 > r1)     s_[j][2] = -1e30f;
                if (k0 + 1 > r1) s_[j][3] = -1e30f;
            }
        }

        // ---- online softmax ----
        float mx0 = -1e30f, mx1 = -1e30f;
#pragma unroll
        for (int j = 0; j < 8; j++) {
            mx0 = fmaxf(mx0, fmaxf(s_[j][0], s_[j][1]));
            mx1 = fmaxf(mx1, fmaxf(s_[j][2], s_[j][3]));
        }
        mx0 = fmaxf(mx0, __shfl_xor_sync(0xffffffffu, mx0, 1));
        mx0 = fmaxf(mx0, __shfl_xor_sync(0xffffffffu, mx0, 2));
        mx1 = fmaxf(mx1, __shfl_xor_sync(0xffffffffu, mx1, 1));
        mx1 = fmaxf(mx1, __shfl_xor_sync(0xffffffffu, mx1, 2));

        const float mn0 = fmaxf(m0, mx0), mn1 = fmaxf(m1, mx1);
        const float ex0 = __expf(m0 - mn0), ex1 = __expf(m1 - mn1);
        float rs0 = 0.f, rs1 = 0.f;
#pragma unroll
        for (int j = 0; j < 8; j++) {
            s_[j][0] = rna_tf32(__expf(s_[j][0] - mn0));
            s_[j][1] = rna_tf32(__expf(s_[j][1] - mn0));
            s_[j][2] = rna_tf32(__expf(s_[j][2] - mn1));
            s_[j][3] = rna_tf32(__expf(s_[j][3] - mn1));
            rs0 += s_[j][0] + s_[j][1];
            rs1 += s_[j][2] + s_[j][3];
        }
        rs0 += __shfl_xor_sync(0xffffffffu, rs0, 1);
        rs0 += __shfl_xor_sync(0xffffffffu, rs0, 2);
        rs1 += __shfl_xor_sync(0xffffffffu, rs1, 1);
        rs1 += __shfl_xor_sync(0xffffffffu, rs1, 2);
        l0 = l0 * ex0 + rs0;  m0 = mn0;
        l1 = l1 * ex1 + rs1;  m1 = mn1;
#pragma unroll
        for (int j = 0; j < 8; j++) {
            o_[j][0] *= ex0; o_[j][1] *= ex0;
            o_[j][2] *= ex1; o_[j][3] *= ex1;
        }

        // ---- P -> smem (per-warp rows; same-warp consumer) ----
#pragma unroll
        for (int j = 0; j < 8; j++) {
            *(float2*)&Ps[(w16 + g) * PADK + j * 8 + 2 * q] =
                make_float2(s_[j][0], s_[j][1]);
            *(float2*)&Ps[(w16 + g + 8) * PADK + j * 8 + 2 * q] =
                make_float2(s_[j][2], s_[j][3]);
        }
        __syncwarp();

        // ---- O += P V  (V read directly from natural layout, CF banks) ----
        const float* Vb = Vs + s * VS_F;
#pragma unroll
        for (int ks = 0; ks < 8; ks++) {
            uint32_t a[4];
            const int k0 = ks * 8 + q;
            a[0] = __float_as_uint(Ps[(w16 + g) * PADK + k0]);
            a[1] = __float_as_uint(Ps[(w16 + g + 8) * PADK + k0]);
            a[2] = __float_as_uint(Ps[(w16 + g) * PADK + k0 + 4]);
            a[3] = __float_as_uint(Ps[(w16 + g + 8) * PADK + k0 + 4]);
            const float* Vr0 = Vb + (ks * 8 + q) * PADV + g;
            const float* Vr1 = Vb + (ks * 8 + q + 4) * PADV + g;
#pragma unroll
            for (int j = 0; j < 8; j++) {
                const uint32_t b0 = __float_as_uint(Vr0[j * 8]);
                const uint32_t b1 = __float_as_uint(Vr1[j * 8]);
                mma_tf32_b(o_[j], a, b0, b1);
            }
        }

        // ---- prefetch K/V(kt+2) into buffer s (all warps done reading s) ----
        if (kt + 2 < nkt) {
            __syncthreads();
            load_kv(kt + 2, s);
        }
    }

    // ---- epilogue ----
    const int b = bh >> 4, h = bh & 15;
    const float inv0 = 1.f / l0, inv1 = 1.f / l1;
    const int t0 = qt * 128 + w16 + g;
    float* dst0 = g_o + ((size_t)(b * T_ + t0)) * D_ + h * 64;
    float* dst1 = g_o + ((size_t)(b * T_ + t0 + 8)) * D_ + h * 64;
#pragma unroll
    for (int j = 0; j < 8; j++) {
        *(float2*)(dst0 + j * 8 + 2 * q) =
            make_float2(rna_tf32(o_[j][0] * inv0), rna_tf32(o_[j][1] * inv0));
        *(float2*)(dst1 + j * 8 + 2 * q) =
            make_float2(rna_tf32(o_[j][2] * inv1), rna_tf32(o_[j][3] * inv1));
    }
}

// ---------------------------------------------------------------------------
// Launch
// ---------------------------------------------------------------------------
extern "C" void kernel_launch(void* const* d_in, const int* in_sizes, int n_in,
                              void* d_out, int out_size) {
    const float* x  = (const float*)d_in[0];
    const float* Wk = (const float*)d_in[1];
    const float* Wq = (const float*)d_in[2];
    const float* Wv = (const float*)d_in[3];
    const float* Wp = (const float*)d_in[4];
    const float* bp = (const float*)d_in[5];
    float* out = (float*)d_out;

    float *qp, *kp, *vp, *op, *xr, *wr;
    cudaGetSymbolAddress((void**)&qp, g_q);
    cudaGetSymbolAddress((void**)&kp, g_k);
    cudaGetSymbolAddress((void**)&vp, g_v);
    cudaGetSymbolAddress((void**)&op, g_o);
    cudaGetSymbolAddress((void**)&xr, g_xr);
    cudaGetSymbolAddress((void**)&wr, g_wr);

    cudaFuncSetAttribute(gemm_qkv, cudaFuncAttributeMaxDynamicSharedMemorySize, GSMEM);
    cudaFuncSetAttribute(gemm_out, cudaFuncAttributeMaxDynamicSharedMemorySize, GSMEM);
    cudaFuncSetAttribute(flash_mma, cudaFuncAttributeMaxDynamicSharedMemorySize, FL_SMEM);

    const int NX = B_ * T_ * D_;
    const int NW = D_ * D_;

    // rounding
    round_tf32<<<NX / 1024, 256>>>(x, xr);
    WPtrs ws; ws.w[0] = Wk; ws.w[1] = Wq; ws.w[2] = Wv; ws.w[3] = Wp;
    round_w4<<<dim3(NW / 1024, 4), 256>>>(ws, wr);

    // fused QKV projections
    gemm_qkv<<<dim3(D_ / 128, M_ / 128, 3), 128, GSMEM>>>(xr, wr, kp, qp, vp);

    // flash attention v4
    flash_mma<<<dim3(T_ / 128, B_ * H_), 256, FL_SMEM>>>();

    // output projection
    gemm_out<<<dim3(D_ / 128, M_ / 128), 128, GSMEM>>>(op, wr + 3 * (size_t)NW, out, bp);
}

// round 14
// speedup vs baseline: 1.1744x; 1.0423x over previous
#include <cuda_runtime.h>
#include <cstdint>

// Problem constants
#define B_  4
#define T_  2048
#define D_  1024
#define H_  16
#define HD_ 64
#define M_  (B_*T_)   // 8192

// Scratch buffers
__device__ float g_q[(size_t)B_*H_*T_*HD_];
__device__ float g_k[(size_t)B_*H_*T_*HD_];
__device__ float g_v[(size_t)B_*H_*T_*HD_];
__device__ float g_o[(size_t)B_*T_*D_];
__device__ float g_xr[(size_t)B_*T_*D_];     // tf32-rounded activations
__device__ float g_wr[(size_t)4*D_*D_];      // tf32-rounded weights (k,q,v,p)

// ---------------------------------------------------------------------------
// helpers
// ---------------------------------------------------------------------------
__device__ __forceinline__ uint32_t smem_u32(const void* p) {
    uint32_t a;
    asm("{ .reg .u64 t; cvta.to.shared.u64 t, %1; cvt.u32.u64 %0, t; }"
        : "=r"(a) : "l"(p));
    return a;
}

__device__ __forceinline__ void cp_async16(uint32_t dst, const void* src) {
    asm volatile("cp.async.cg.shared.global [%0], [%1], 16;" :: "r"(dst), "l"(src));
}

__device__ __forceinline__ void mma_tf32(float* c, const uint32_t* a, const uint32_t* b) {
    asm volatile(
        "mma.sync.aligned.m16n8k8.row.col.f32.tf32.tf32.f32 "
        "{%0,%1,%2,%3}, {%4,%5,%6,%7}, {%8,%9}, {%0,%1,%2,%3};"
        : "+f"(c[0]), "+f"(c[1]), "+f"(c[2]), "+f"(c[3])
        : "r"(a[0]), "r"(a[1]), "r"(a[2]), "r"(a[3]), "r"(b[0]), "r"(b[1]));
}

__device__ __forceinline__ void mma_tf32_b(float* c, const uint32_t* a,
                                           uint32_t b0, uint32_t b1) {
    asm volatile(
        "mma.sync.aligned.m16n8k8.row.col.f32.tf32.tf32.f32 "
        "{%0,%1,%2,%3}, {%4,%5,%6,%7}, {%8,%9}, {%0,%1,%2,%3};"
        : "+f"(c[0]), "+f"(c[1]), "+f"(c[2]), "+f"(c[3])
        : "r"(a[0]), "r"(a[1]), "r"(a[2]), "r"(a[3]), "r"(b0), "r"(b1));
}

__device__ __forceinline__ float rna_tf32(float x) {
    uint32_t u;
    asm("cvt.rna.tf32.f32 %0, %1;" : "=r"(u) : "f"(x));
    return __uint_as_float(u);
}

// ---------------------------------------------------------------------------
// tf32 pre-rounding
// ---------------------------------------------------------------------------
__global__ void __launch_bounds__(256) round_tf32(const float* __restrict__ x,
                                                  float* __restrict__ y) {
    const size_t i = ((size_t)blockIdx.x * 256 + threadIdx.x) * 4;
    float4 v = *(const float4*)(x + i);
    float4 o;
    o.x = rna_tf32(v.x); o.y = rna_tf32(v.y);
    o.z = rna_tf32(v.z); o.w = rna_tf32(v.w);
    *(float4*)(y + i) = o;
}

struct WPtrs { const float* w[4]; };
__global__ void __launch_bounds__(256) round_w4(WPtrs ws, float* __restrict__ y) {
    const int z = blockIdx.y;
    const float* src = ws.w[z];
    float* dst = y + (size_t)z * D_ * D_;
    const size_t i = ((size_t)blockIdx.x * 256 + threadIdx.x) * 4;
    float4 v = *(const float4*)(src + i);
    float4 o;
    o.x = rna_tf32(v.x); o.y = rna_tf32(v.y);
    o.z = rna_tf32(v.z); o.w = rna_tf32(v.w);
    *(float4*)(dst + i) = o;
}

// ---------------------------------------------------------------------------
// GEMM (unchanged — known good)
// ---------------------------------------------------------------------------
#define SROW   36
#define STG_F  (128 * SROW)
#define STAGE_F (2 * STG_F)
#define GSMEM  (3 * STAGE_F * 4)   // 110592 B

template<int MODE>
__device__ __forceinline__ void gemm_body(const float* __restrict__ A,
                                          const float* __restrict__ W,
                                          float* __restrict__ out,
                                          const float* __restrict__ bias,
                                          float* sm, int bx, int by) {
    const int tid  = threadIdx.x;
    const int lane = tid & 31;
    const int wid  = tid >> 5;
    const int wm   = wid >> 1;
    const int wn   = wid & 1;

    float c[4][8][4];
#pragma unroll
    for (int i = 0; i < 4; i++)
#pragma unroll
        for (int j = 0; j < 8; j++)
#pragma unroll
            for (int k = 0; k < 4; k++) c[i][j][k] = 0.f;

    const int lr = tid >> 3;
    const int ls = tid & 7;
    const float* Ag = A + (size_t)(by * 128 + lr) * 1024 + ls * 4;
    const float* Wg = W + (size_t)(bx * 128 + lr) * 1024 + ls * 4;

    const uint32_t ldst = smem_u32(sm) + (lr * SROW + ls * 4) * 4;

    auto load_tile = [&](int kt, int s) {
        const uint32_t aB = ldst + (uint32_t)s * (STAGE_F * 4);
        const uint32_t bB = aB + STG_F * 4;
        const float* Ak = Ag + kt * 32;
        const float* Wk = Wg + kt * 32;
#pragma unroll
        for (int i = 0; i < 8; i++) {
            cp_async16(aB + i * 16 * (SROW * 4), Ak + (size_t)i * 16 * 1024);
            cp_async16(bB + i * 16 * (SROW * 4), Wk + (size_t)i * 16 * 1024);
        }
        asm volatile("cp.async.commit_group;" ::: "memory");
    };

    load_tile(0, 0);
    load_tile(1, 1);

    const int g = lane >> 2;
    const int q = lane & 3;

    uint32_t af[2][4][4], bf[2][8][2];

    auto frag_load = [&](const uint32_t* As, const uint32_t* Bs, int ks, int buf) {
        const int k0 = ks * 8 + q;
#pragma unroll
        for (int mm = 0; mm < 4; mm++) {
            af[buf][mm][0] = As[(mm * 16)     * SROW + k0];
            af[buf][mm][1] = As[(mm * 16 + 8) * SROW + k0];
            af[buf][mm][2] = As[(mm * 16)     * SROW + k0 + 4];
            af[buf][mm][3] = As[(mm * 16 + 8) * SROW + k0 + 4];
        }
#pragma unroll
        for (int nn = 0; nn < 8; nn++) {
            bf[buf][nn][0] = Bs[(nn * 8) * SROW + k0];
            bf[buf][nn][1] = Bs[(nn * 8) * SROW + k0 + 4];
        }
    };

    int s = 0, sl = 2;
    for (int kt = 0; kt < 32; kt++) {
        if (kt < 31) {
            asm volatile("cp.async.wait_group 1;" ::: "memory");
        } else {
            asm volatile("cp.async.wait_group 0;" ::: "memory");
        }
        __syncthreads();

        if (kt + 2 < 32) {
            load_tile(kt + 2, sl);
            sl = (sl == 2) ? 0 : sl + 1;
        }

        const uint32_t* As = (const uint32_t*)(sm + s * STAGE_F) +
                             (wm * 64 + g) * SROW;
        const uint32_t* Bs = (const uint32_t*)(sm + s * STAGE_F + STG_F) +
                             (wn * 64 + g) * SROW;

        frag_load(As, Bs, 0, 0);
#pragma unroll
        for (int ks = 0; ks < 4; ks++) {
            const int cur = ks & 1;
            if (ks < 3) frag_load(As, Bs, ks + 1, cur ^ 1);
#pragma unroll
            for (int mm = 0; mm < 4; mm++)
#pragma unroll
                for (int nn = 0; nn < 8; nn++)
                    mma_tf32(c[mm][nn], af[cur][mm], bf[cur][nn]);
        }
        s = (s == 2) ? 0 : s + 1;
    }

    const int rbase = by * 128 + wm * 64 + g;
    const int cbase = bx * 128 + wn * 64 + 2 * q;
#pragma unroll
    for (int mm = 0; mm < 4; mm++) {
        const int r0 = rbase + mm * 16;
#pragma unroll
        for (int nn = 0; nn < 8; nn++) {
            const int cc = cbase + nn * 8;
            if (MODE == 0) {
                const int h = cc >> 6, d = cc & 63;
                const int b = r0 >> 11, t = r0 & 2047;
                float* dst = out + (((size_t)(b * H_ + h)) * T_ + t) * HD_ + d;
                *(float2*)dst =
                    make_float2(rna_tf32(c[mm][nn][0]), rna_tf32(c[mm][nn][1]));
                *(float2*)(dst + 8 * HD_) =
                    make_float2(rna_tf32(c[mm][nn][2]), rna_tf32(c[mm][nn][3]));
            } else {
                float2 bb = *(const float2*)(bias + cc);
                float* dst = out + (size_t)r0 * 1024 + cc;
                *(float2*)dst = make_float2(c[mm][nn][0] + bb.x, c[mm][nn][1] + bb.y);
                *(float2*)(dst + 8 * 1024) =
                    make_float2(c[mm][nn][2] + bb.x, c[mm][nn][3] + bb.y);
            }
        }
    }
}

__global__ void __launch_bounds__(128) gemm_qkv(const float* __restrict__ A,
                                                const float* __restrict__ Wr,
                                                float* __restrict__ o0,
                                                float* __restrict__ o1,
                                                float* __restrict__ o2) {
    extern __shared__ float sm[];
    const int z = blockIdx.z;
    const float* W = Wr + (size_t)z * D_ * D_;
    float* out = (z == 0) ? o0 : (z == 1) ? o1 : o2;
    gemm_body<0>(A, W, out, nullptr, sm, blockIdx.x, blockIdx.y);
}

__global__ void __launch_bounds__(128) gemm_out(const float* __restrict__ A,
                                                const float* __restrict__ W,
                                                float* __restrict__ out,
                                                const float* __restrict__ bias) {
    extern __shared__ float sm[];
    gemm_body<1>(A, W, out, bias, sm, blockIdx.x, blockIdx.y);
}

// ---------------------------------------------------------------------------
// Flash attention v5: NO P smem round-trip.  The softmax'd S C-fragment is
// fed DIRECTLY as the PV A-operand (a = {s0,s2,s1,s3}); correctness restored
// by storing V rows permuted within each 8-key group (even keys -> slots 0-3,
// odd -> slots 4-7), so slot row (8ks+q) holds key (8ks+2q).  PV read
// addresses identical to v4 (conflict-free).  K/V triple-buffered ->
// ONE __syncthreads per tile.  Q in registers (pre-scaled).
// smem: Ks[3][64*68] + Vs[3][64*72] = 107520 B -> 2 CTAs/SM.
// ---------------------------------------------------------------------------
#define PADK 68
#define PADV 72
#define KS_F (64 * PADK)   // 4352
#define VS_F (64 * PADV)   // 4608
#define FL_SMEM ((3 * KS_F + 3 * VS_F) * 4)   // 107520

__global__ void __launch_bounds__(256, 2) flash_mma() {
    extern __shared__ float sm[];
    float* Ks = sm;                 // [3][64][PADK]
    float* Vs = sm + 3 * KS_F;      // [3][64][PADV] (row-permuted)
    float* Qstage = Vs + VS_F;      // staging in Vs[1..2] area (pre-pipeline)

    const int tid = threadIdx.x, lane = tid & 31, wid = tid >> 5;
    const int g = lane >> 2, q = lane & 3;
    const int qt = blockIdx.x, bh = blockIdx.y;
    const int w16 = wid * 16;

    const float* Qg = g_q + (size_t)bh * T_ * HD_ + (size_t)qt * 128 * HD_;
    const float* Kg = g_k + (size_t)bh * T_ * HD_;
    const float* Vg = g_v + (size_t)bh * T_ * HD_;

    const uint32_t sb  = smem_u32(sm);
    const uint32_t VsB = sb + 3 * KS_F * 4;
    const uint32_t QsB = VsB + VS_F * 4;

    const int lrow = tid >> 4;       // 0..15
    const int lchk = tid & 15;       // 16B chunk in 64-float row

    auto load_kv = [&](int kt, int s) {
        const float* Kt = Kg + (size_t)kt * 64 * 64;
        const float* Vt = Vg + (size_t)kt * 64 * 64;
        const uint32_t kB = sb + (uint32_t)s * (KS_F * 4);
        const uint32_t vB = VsB + (uint32_t)s * (VS_F * 4);
#pragma unroll
        for (int i = 0; i < 4; i++) {
            const int r = lrow + i * 16;
            // V row permutation: key r -> slot (r&56) | ((r&1)<<2) | ((r>>1)&3)
            const int pr = (r & 56) | ((r & 1) << 2) | ((r >> 1) & 3);
            cp_async16(kB + (r * PADK + lchk * 4) * 4, Kt + r * 64 + lchk * 4);
            cp_async16(vB + (pr * PADV + lchk * 4) * 4, Vt + r * 64 + lchk * 4);
        }
        asm volatile("cp.async.commit_group;" ::: "memory");
    };

    // ---- prologue ----
    {   // group 0: Q -> Qstage
        const int row = tid >> 1, segb = (tid & 1) * 8;
#pragma unroll
        for (int i = 0; i < 8; i++)
            cp_async16(QsB + (row * PADK + (segb + i) * 4) * 4,
                       Qg + row * 64 + (segb + i) * 4);
        asm volatile("cp.async.commit_group;" ::: "memory");
    }
    load_kv(0, 0);                                          // group 1
    asm volatile("cp.async.wait_group 1;" ::: "memory");    // Q done
    __syncthreads();

    // Q fragments to registers, pre-scaled by 1/sqrt(hd) (exact)
    uint32_t qf[8][4];
#pragma unroll
    for (int ks = 0; ks < 8; ks++) {
        qf[ks][0] = __float_as_uint(Qstage[(w16 + g) * PADK + ks * 8 + q] * 0.125f);
        qf[ks][1] = __float_as_uint(Qstage[(w16 + g + 8) * PADK + ks * 8 + q] * 0.125f);
        qf[ks][2] = __float_as_uint(Qstage[(w16 + g) * PADK + ks * 8 + q + 4] * 0.125f);
        qf[ks][3] = __float_as_uint(Qstage[(w16 + g + 8) * PADK + ks * 8 + q + 4] * 0.125f);
    }
    __syncthreads();             // all warps done reading Qstage
    const int nkt = 2 * qt + 2;
    load_kv(1, 1);               // group 2 (overwrites part of Qstage — safe)

    float o_[8][4];
#pragma unroll
    for (int j = 0; j < 8; j++)
#pragma unroll
        for (int k = 0; k < 4; k++) o_[j][k] = 0.f;
    float m0 = -1e30f, m1 = -1e30f, l0 = 0.f, l1 = 0.f;

    for (int kt = 0; kt < nkt; kt++) {
        const int s = kt % 3;

        asm volatile("cp.async.wait_group 1;" ::: "memory");  // K/V(kt) arrived
        __syncthreads();   // everyone finished iter kt-1 -> buffer (kt+2)%3 free
        if (kt + 2 < nkt) load_kv(kt + 2, (kt + 2) % 3);

        // ---- S = Q K^T ----
        float s_[8][4];
#pragma unroll
        for (int j = 0; j < 8; j++)
#pragma unroll
            for (int k = 0; k < 4; k++) s_[j][k] = 0.f;

        const float* Kb = Ks + s * KS_F;
#pragma unroll
        for (int ks = 0; ks < 8; ks++) {
#pragma unroll
            for (int j = 0; j < 8; j++) {
                const uint32_t b0 = __float_as_uint(Kb[(j * 8 + g) * PADK + ks * 8 + q]);
                const uint32_t b1 = __float_as_uint(Kb[(j * 8 + g) * PADK + ks * 8 + q + 4]);
                mma_tf32_b(s_[j], qf[ks], b0, b1);
            }
        }

        // ---- causal mask (last two tiles only; S pre-scaled via Q) ----
        if (kt >= 2 * qt) {
            const int kb2 = kt * 64;
            const int r0 = qt * 128 + w16 + g, r1 = r0 + 8;
#pragma unroll
            for (int j = 0; j < 8; j++) {
                const int k0 = kb2 + j * 8 + 2 * q;
                if (k0 > r0)     s_[j][0] = -1e30f;
                if (k0 + 1 > r0) s_[j][1] = -1e30f;
                if (k0 > r1)     s_[j][2] = -1e30f;
                if (k0 + 1 > r1) s_[j][3] = -1e30f;
            }
        }

        // ---- online softmax ----
        float mx0 = -1e30f, mx1 = -1e30f;
#pragma unroll
        for (int j = 0; j < 8; j++) {
            mx0 = fmaxf(mx0, fmaxf(s_[j][0], s_[j][1]));
            mx1 = fmaxf(mx1, fmaxf(s_[j][2], s_[j][3]));
        }
        mx0 = fmaxf(mx0, __shfl_xor_sync(0xffffffffu, mx0, 1));
        mx0 = fmaxf(mx0, __shfl_xor_sync(0xffffffffu, mx0, 2));
        mx1 = fmaxf(mx1, __shfl_xor_sync(0xffffffffu, mx1, 1));
        mx1 = fmaxf(mx1, __shfl_xor_sync(0xffffffffu, mx1, 2));

        const float mn0 = fmaxf(m0, mx0), mn1 = fmaxf(m1, mx1);
        const float ex0 = __expf(m0 - mn0), ex1 = __expf(m1 - mn1);
        float rs0 = 0.f, rs1 = 0.f;
#pragma unroll
        for (int j = 0; j < 8; j++) {
            s_[j][0] = rna_tf32(__expf(s_[j][0] - mn0));
            s_[j][1] = rna_tf32(__expf(s_[j][1] - mn0));
            s_[j][2] = rna_tf32(__expf(s_[j][2] - mn1));
            s_[j][3] = rna_tf32(__expf(s_[j][3] - mn1));
            rs0 += s_[j][0] + s_[j][1];
            rs1 += s_[j][2] + s_[j][3];
        }
        rs0 += __shfl_xor_sync(0xffffffffu, rs0, 1);
        rs0 += __shfl_xor_sync(0xffffffffu, rs0, 2);
        rs1 += __shfl_xor_sync(0xffffffffu, rs1, 1);
        rs1 += __shfl_xor_sync(0xffffffffu, rs1, 2);
        l0 = l0 * ex0 + rs0;  m0 = mn0;
        l1 = l1 * ex1 + rs1;  m1 = mn1;
#pragma unroll
        for (int j = 0; j < 8; j++) {
            o_[j][0] *= ex0; o_[j][1] *= ex0;
            o_[j][2] *= ex1; o_[j][3] *= ex1;
        }

        // ---- O += P V : C-fragment fed directly as A (V rows permuted) ----
        const float* Vb = Vs + s * VS_F;
#pragma unroll
        for (int ks = 0; ks < 8; ks++) {
            uint32_t a[4];
            a[0] = __float_as_uint(s_[ks][0]);   // A[g][q]     = P[g][8ks+2q]
            a[1] = __float_as_uint(s_[ks][2]);   // A[g+8][q]   = P[g+8][8ks+2q]
            a[2] = __float_as_uint(s_[ks][1]);   // A[g][q+4]   = P[g][8ks+2q+1]
            a[3] = __float_as_uint(s_[ks][3]);   // A[g+8][q+4] = P[g+8][8ks+2q+1]
            const float* Vr0 = Vb + (ks * 8 + q) * PADV + g;      // key 8ks+2q
            const float* Vr1 = Vb + (ks * 8 + q + 4) * PADV + g;  // key 8ks+2q+1
#pragma unroll
            for (int j = 0; j < 8; j++) {
                const uint32_t b0 = __float_as_uint(Vr0[j * 8]);
                const uint32_t b1 = __float_as_uint(Vr1[j * 8]);
                mma_tf32_b(o_[j], a, b0, b1);
            }
        }
    }

    // ---- epilogue ----
    const int b = bh >> 4, h = bh & 15;
    const float inv0 = 1.f / l0, inv1 = 1.f / l1;
    const int t0 = qt * 128 + w16 + g;
    float* dst0 = g_o + ((size_t)(b * T_ + t0)) * D_ + h * 64;
    float* dst1 = g_o + ((size_t)(b * T_ + t0 + 8)) * D_ + h * 64;
#pragma unroll
    for (int j = 0; j < 8; j++) {
        *(float2*)(dst0 + j * 8 + 2 * q) =
            make_float2(rna_tf32(o_[j][0] * inv0), rna_tf32(o_[j][1] * inv0));
        *(float2*)(dst1 + j * 8 + 2 * q) =
            make_float2(rna_tf32(o_[j][2] * inv1), rna_tf32(o_[j][3] * inv1));
    }
}

// ---------------------------------------------------------------------------
// Launch
// ---------------------------------------------------------------------------
extern "C" void kernel_launch(void* const* d_in, const int* in_sizes, int n_in,
                              void* d_out, int out_size) {
    const float* x  = (const float*)d_in[0];
    const float* Wk = (const float*)d_in[1];
    const float* Wq = (const float*)d_in[2];
    const float* Wv = (const float*)d_in[3];
    const float* Wp = (const float*)d_in[4];
    const float* bp = (const float*)d_in[5];
    float* out = (float*)d_out;

    float *qp, *kp, *vp, *op, *xr, *wr;
    cudaGetSymbolAddress((void**)&qp, g_q);
    cudaGetSymbolAddress((void**)&kp, g_k);
    cudaGetSymbolAddress((void**)&vp, g_v);
    cudaGetSymbolAddress((void**)&op, g_o);
    cudaGetSymbolAddress((void**)&xr, g_xr);
    cudaGetSymbolAddress((void**)&wr, g_wr);

    cudaFuncSetAttribute(gemm_qkv, cudaFuncAttributeMaxDynamicSharedMemorySize, GSMEM);
    cudaFuncSetAttribute(gemm_out, cudaFuncAttributeMaxDynamicSharedMemorySize, GSMEM);
    cudaFuncSetAttribute(flash_mma, cudaFuncAttributeMaxDynamicSharedMemorySize, FL_SMEM);

    const int NX = B_ * T_ * D_;
    const int NW = D_ * D_;

    // rounding
    round_tf32<<<NX / 1024, 256>>>(x, xr);
    WPtrs ws; ws.w[0] = Wk; ws.w[1] = Wq; ws.w[2] = Wv; ws.w[3] = Wp;
    round_w4<<<dim3(NW / 1024, 4), 256>>>(ws, wr);

    // fused QKV projections
    gemm_qkv<<<dim3(D_ / 128, M_ / 128, 3), 128, GSMEM>>>(xr, wr, kp, qp, vp);

    // flash attention v5
    flash_mma<<<dim3(T_ / 128, B_ * H_), 256, FL_SMEM>>>();

    // output projection
    gemm_out<<<dim3(D_ / 128, M_ / 128), 128, GSMEM>>>(op, wr + 3 * (size_t)NW, out, bp);
}

// round 15
// speedup vs baseline: 1.2524x; 1.0664x over previous
#include <cuda_runtime.h>
#include <cstdint>

// Problem constants
#define B_  4
#define T_  2048
#define D_  1024
#define H_  16
#define HD_ 64
#define M_  (B_*T_)   // 8192

// Scratch buffers
__device__ float g_q[(size_t)B_*H_*T_*HD_];
__device__ float g_k[(size_t)B_*H_*T_*HD_];
__device__ float g_v[(size_t)B_*H_*T_*HD_];
__device__ float g_o[(size_t)B_*T_*D_];
__device__ float g_xr[(size_t)B_*T_*D_];     // tf32-rounded activations
__device__ float g_wr[(size_t)4*D_*D_];      // tf32-rounded weights (k,q,v,p)

// ---------------------------------------------------------------------------
// helpers
// ---------------------------------------------------------------------------
__device__ __forceinline__ uint32_t smem_u32(const void* p) {
    uint32_t a;
    asm("{ .reg .u64 t; cvta.to.shared.u64 t, %1; cvt.u32.u64 %0, t; }"
        : "=r"(a) : "l"(p));
    return a;
}

__device__ __forceinline__ void cp_async16(uint32_t dst, const void* src) {
    asm volatile("cp.async.cg.shared.global [%0], [%1], 16;" :: "r"(dst), "l"(src));
}

// ldmatrix x4: four 8x8 b16 matrices == tf32 fragments (1 tf32/lane/matrix).
__device__ __forceinline__ void ldsm_x4(uint32_t& r0, uint32_t& r1,
                                        uint32_t& r2, uint32_t& r3, uint32_t addr) {
    asm volatile("ldmatrix.sync.aligned.m8n8.x4.shared.b16 {%0,%1,%2,%3}, [%4];"
                 : "=r"(r0), "=r"(r1), "=r"(r2), "=r"(r3) : "r"(addr));
}

__device__ __forceinline__ void mma_tf32(float* c, const uint32_t* a, const uint32_t* b) {
    asm volatile(
        "mma.sync.aligned.m16n8k8.row.col.f32.tf32.tf32.f32 "
        "{%0,%1,%2,%3}, {%4,%5,%6,%7}, {%8,%9}, {%0,%1,%2,%3};"
        : "+f"(c[0]), "+f"(c[1]), "+f"(c[2]), "+f"(c[3])
        : "r"(a[0]), "r"(a[1]), "r"(a[2]), "r"(a[3]), "r"(b[0]), "r"(b[1]));
}

__device__ __forceinline__ void mma_tf32_b(float* c, const uint32_t* a,
                                           uint32_t b0, uint32_t b1) {
    asm volatile(
        "mma.sync.aligned.m16n8k8.row.col.f32.tf32.tf32.f32 "
        "{%0,%1,%2,%3}, {%4,%5,%6,%7}, {%8,%9}, {%0,%1,%2,%3};"
        : "+f"(c[0]), "+f"(c[1]), "+f"(c[2]), "+f"(c[3])
        : "r"(a[0]), "r"(a[1]), "r"(a[2]), "r"(a[3]), "r"(b0), "r"(b1));
}

__device__ __forceinline__ float rna_tf32(float x) {
    uint32_t u;
    asm("cvt.rna.tf32.f32 %0, %1;" : "=r"(u) : "f"(x));
    return __uint_as_float(u);
}

// ---------------------------------------------------------------------------
// tf32 pre-rounding
// ---------------------------------------------------------------------------
__global__ void __launch_bounds__(256) round_tf32(const float* __restrict__ x,
                                                  float* __restrict__ y) {
    const size_t i = ((size_t)blockIdx.x * 256 + threadIdx.x) * 4;
    float4 v = *(const float4*)(x + i);
    float4 o;
    o.x = rna_tf32(v.x); o.y = rna_tf32(v.y);
    o.z = rna_tf32(v.z); o.w = rna_tf32(v.w);
    *(float4*)(y + i) = o;
}

struct WPtrs { const float* w[4]; };
__global__ void __launch_bounds__(256) round_w4(WPtrs ws, float* __restrict__ y) {
    const int z = blockIdx.y;
    const float* src = ws.w[z];
    float* dst = y + (size_t)z * D_ * D_;
    const size_t i = ((size_t)blockIdx.x * 256 + threadIdx.x) * 4;
    float4 v = *(const float4*)(src + i);
    float4 o;
    o.x = rna_tf32(v.x); o.y = rna_tf32(v.y);
    o.z = rna_tf32(v.z); o.w = rna_tf32(v.w);
    *(float4*)(dst + i) = o;
}

// ---------------------------------------------------------------------------
// GEMM with ldmatrix fragment loads.
// CTA 128x128, 4 warps (2x2), warp tile 64x64, BK=32, 3-stage cp.async.
// ---------------------------------------------------------------------------
#define SROW   36
#define STG_F  (128 * SROW)
#define STAGE_F (2 * STG_F)
#define GSMEM  (3 * STAGE_F * 4)   // 110592 B

template<int MODE>
__device__ __forceinline__ void gemm_body(const float* __restrict__ A,
                                          const float* __restrict__ W,
                                          float* __restrict__ out,
                                          const float* __restrict__ bias,
                                          float* sm, int bx, int by) {
    const int tid  = threadIdx.x;
    const int lane = tid & 31;
    const int wid  = tid >> 5;
    const int wm   = wid >> 1;
    const int wn   = wid & 1;

    float c[4][8][4];
#pragma unroll
    for (int i = 0; i < 4; i++)
#pragma unroll
        for (int j = 0; j < 8; j++)
#pragma unroll
            for (int k = 0; k < 4; k++) c[i][j][k] = 0.f;

    const int lr = tid >> 3;
    const int ls = tid & 7;
    const float* Ag = A + (size_t)(by * 128 + lr) * 1024 + ls * 4;
    const float* Wg = W + (size_t)(bx * 128 + lr) * 1024 + ls * 4;

    const uint32_t sbase = smem_u32(sm);
    const uint32_t ldst  = sbase + (lr * SROW + ls * 4) * 4;

    auto load_tile = [&](int kt, int s) {
        const uint32_t aB = ldst + (uint32_t)s * (STAGE_F * 4);
        const uint32_t bB = aB + STG_F * 4;
        const float* Ak = Ag + kt * 32;
        const float* Wk = Wg + kt * 32;
#pragma unroll
        for (int i = 0; i < 8; i++) {
            cp_async16(aB + i * 16 * (SROW * 4), Ak + (size_t)i * 16 * 1024);
            cp_async16(bB + i * 16 * (SROW * 4), Wk + (size_t)i * 16 * 1024);
        }
        asm volatile("cp.async.commit_group;" ::: "memory");
    };

    load_tile(0, 0);
    load_tile(1, 1);

    // ldmatrix per-thread base offsets:
    // A: lanes 0-15 -> rows 0-15 @ k0, lanes 16-31 -> rows 0-15 @ k0+4
    // B: lanes {0-7,8-15,16-23,24-31} -> rows(+0/+0/+8/+8) @ k {0,+4,0,+4}
    const uint32_t aOff = (uint32_t)(((wm * 64 + (lane & 15)) * SROW +
                                      ((lane >> 4) << 2)) * 4);
    const uint32_t bOff = (uint32_t)((STG_F + ((wn * 64 + (lane & 7) +
                                      ((lane >> 4) << 3)) * SROW) +
                                      (((lane >> 3) & 1) << 2)) * 4);

    const int q = lane & 3;   // for epilogue indexing
    const int g = lane >> 2;

    uint32_t af[2][4][4], bf[2][4][4];

    auto frag_load = [&](uint32_t stB, int ks, int buf) {
        const uint32_t ko = (uint32_t)(ks * 8 * 4);
#pragma unroll
        for (int mm = 0; mm < 4; mm++)
            ldsm_x4(af[buf][mm][0], af[buf][mm][1], af[buf][mm][2], af[buf][mm][3],
                    stB + aOff + (uint32_t)(mm * 16 * SROW * 4) + ko);
#pragma unroll
        for (int np = 0; np < 4; np++)
            ldsm_x4(bf[buf][np][0], bf[buf][np][1], bf[buf][np][2], bf[buf][np][3],
                    stB + bOff + (uint32_t)(np * 16 * SROW * 4) + ko);
    };

    int s = 0, sl = 2;
    for (int kt = 0; kt < 32; kt++) {
        if (kt < 31) {
            asm volatile("cp.async.wait_group 1;" ::: "memory");
        } else {
            asm volatile("cp.async.wait_group 0;" ::: "memory");
        }
        __syncthreads();

        if (kt + 2 < 32) {
            load_tile(kt + 2, sl);
            sl = (sl == 2) ? 0 : sl + 1;
        }

        const uint32_t stB = sbase + (uint32_t)s * (STAGE_F * 4);
        frag_load(stB, 0, 0);
#pragma unroll
        for (int ks = 0; ks < 4; ks++) {
            const int cur = ks & 1;
            if (ks < 3) frag_load(stB, ks + 1, cur ^ 1);
#pragma unroll
            for (int mm = 0; mm < 4; mm++)
#pragma unroll
                for (int np = 0; np < 4; np++) {
                    mma_tf32_b(c[mm][2 * np],     af[cur][mm],
                               bf[cur][np][0], bf[cur][np][1]);
                    mma_tf32_b(c[mm][2 * np + 1], af[cur][mm],
                               bf[cur][np][2], bf[cur][np][3]);
                }
        }
        s = (s == 2) ? 0 : s + 1;
    }

    const int rbase = by * 128 + wm * 64 + g;
    const int cbase = bx * 128 + wn * 64 + 2 * q;
#pragma unroll
    for (int mm = 0; mm < 4; mm++) {
        const int r0 = rbase + mm * 16;
#pragma unroll
        for (int nn = 0; nn < 8; nn++) {
            const int cc = cbase + nn * 8;
            if (MODE == 0) {
                const int h = cc >> 6, d = cc & 63;
                const int b = r0 >> 11, t = r0 & 2047;
                float* dst = out + (((size_t)(b * H_ + h)) * T_ + t) * HD_ + d;
                *(float2*)dst =
                    make_float2(rna_tf32(c[mm][nn][0]), rna_tf32(c[mm][nn][1]));
                *(float2*)(dst + 8 * HD_) =
                    make_float2(rna_tf32(c[mm][nn][2]), rna_tf32(c[mm][nn][3]));
            } else {
                float2 bb = *(const float2*)(bias + cc);
                float* dst = out + (size_t)r0 * 1024 + cc;
                *(float2*)dst = make_float2(c[mm][nn][0] + bb.x, c[mm][nn][1] + bb.y);
                *(float2*)(dst + 8 * 1024) =
                    make_float2(c[mm][nn][2] + bb.x, c[mm][nn][3] + bb.y);
            }
        }
    }
}

__global__ void __launch_bounds__(128) gemm_qkv(const float* __restrict__ A,
                                                const float* __restrict__ Wr,
                                                float* __restrict__ o0,
                                                float* __restrict__ o1,
                                                float* __restrict__ o2) {
    extern __shared__ float sm[];
    const int z = blockIdx.z;
    const float* W = Wr + (size_t)z * D_ * D_;
    float* out = (z == 0) ? o0 : (z == 1) ? o1 : o2;
    gemm_body<0>(A, W, out, nullptr, sm, blockIdx.x, blockIdx.y);
}

__global__ void __launch_bounds__(128) gemm_out(const float* __restrict__ A,
                                                const float* __restrict__ W,
                                                float* __restrict__ out,
                                                const float* __restrict__ bias) {
    extern __shared__ float sm[];
    gemm_body<1>(A, W, out, bias, sm, blockIdx.x, blockIdx.y);
}

// ---------------------------------------------------------------------------
// Flash attention v6: v5 + ldmatrix for K fragments.
// smem: Ks[3][64*68] + Vs[3][64*72] = 107520 B -> 2 CTAs/SM.
// ---------------------------------------------------------------------------
#define PADK 68
#define PADV 72
#define KS_F (64 * PADK)
#define VS_F (64 * PADV)
#define FL_SMEM ((3 * KS_F + 3 * VS_F) * 4)   // 107520

__global__ void __launch_bounds__(256, 2) flash_mma() {
    extern __shared__ float sm[];
    float* Vs = sm + 3 * KS_F;
    float* Qstage = Vs + VS_F;

    const int tid = threadIdx.x, lane = tid & 31, wid = tid >> 5;
    const int g = lane >> 2, q = lane & 3;
    const int qt = blockIdx.x, bh = blockIdx.y;
    const int w16 = wid * 16;

    const float* Qg = g_q + (size_t)bh * T_ * HD_ + (size_t)qt * 128 * HD_;
    const float* Kg = g_k + (size_t)bh * T_ * HD_;
    const float* Vg = g_v + (size_t)bh * T_ * HD_;

    const uint32_t sb  = smem_u32(sm);
    const uint32_t VsB = sb + 3 * KS_F * 4;
    const uint32_t QsB = VsB + VS_F * 4;

    const int lrow = tid >> 4;
    const int lchk = tid & 15;

    auto load_kv = [&](int kt, int s) {
        const float* Kt = Kg + (size_t)kt * 64 * 64;
        const float* Vt = Vg + (size_t)kt * 64 * 64;
        const uint32_t kB = sb + (uint32_t)s * (KS_F * 4);
        const uint32_t vB = VsB + (uint32_t)s * (VS_F * 4);
#pragma unroll
        for (int i = 0; i < 4; i++) {
            const int r = lrow + i * 16;
            const int pr = (r & 56) | ((r & 1) << 2) | ((r >> 1) & 3);
            cp_async16(kB + (r * PADK + lchk * 4) * 4, Kt + r * 64 + lchk * 4);
            cp_async16(vB + (pr * PADV + lchk * 4) * 4, Vt + r * 64 + lchk * 4);
        }
        asm volatile("cp.async.commit_group;" ::: "memory");
    };

    // ---- prologue ----
    {
        const int row = tid >> 1, segb = (tid & 1) * 8;
#pragma unroll
        for (int i = 0; i < 8; i++)
            cp_async16(QsB + (row * PADK + (segb + i) * 4) * 4,
                       Qg + row * 64 + (segb + i) * 4);
        asm volatile("cp.async.commit_group;" ::: "memory");
    }
    load_kv(0, 0);
    asm volatile("cp.async.wait_group 1;" ::: "memory");
    __syncthreads();

    uint32_t qf[8][4];
#pragma unroll
    for (int ks = 0; ks < 8; ks++) {
        qf[ks][0] = __float_as_uint(Qstage[(w16 + g) * PADK + ks * 8 + q] * 0.125f);
        qf[ks][1] = __float_as_uint(Qstage[(w16 + g + 8) * PADK + ks * 8 + q] * 0.125f);
        qf[ks][2] = __float_as_uint(Qstage[(w16 + g) * PADK + ks * 8 + q + 4] * 0.125f);
        qf[ks][3] = __float_as_uint(Qstage[(w16 + g + 8) * PADK + ks * 8 + q + 4] * 0.125f);
    }
    __syncthreads();
    const int nkt = 2 * qt + 2;
    load_kv(1, 1);

    // ldmatrix base for K fragments (row-pair form, same as GEMM B operand)
    const uint32_t kOff = (uint32_t)((((lane & 7) + ((lane >> 4) << 3)) * PADK +
                                      (((lane >> 3) & 1) << 2)) * 4);

    float o_[8][4];
#pragma unroll
    for (int j = 0; j < 8; j++)
#pragma unroll
        for (int k = 0; k < 4; k++) o_[j][k] = 0.f;
    float m0 = -1e30f, m1 = -1e30f, l0 = 0.f, l1 = 0.f;

    for (int kt = 0; kt < nkt; kt++) {
        const int s = kt % 3;

        asm volatile("cp.async.wait_group 1;" ::: "memory");
        __syncthreads();
        if (kt + 2 < nkt) load_kv(kt + 2, (kt + 2) % 3);

        // ---- S = Q K^T (K fragments via ldmatrix) ----
        float s_[8][4];
#pragma unroll
        for (int j = 0; j < 8; j++)
#pragma unroll
            for (int k = 0; k < 4; k++) s_[j][k] = 0.f;

        const uint32_t kStage = sb + (uint32_t)s * (KS_F * 4) + kOff;
#pragma unroll
        for (int ks = 0; ks < 8; ks++) {
            const uint32_t ko = kStage + (uint32_t)(ks * 8 * 4);
#pragma unroll
            for (int jp = 0; jp < 4; jp++) {
                uint32_t b00, b01, b10, b11;
                ldsm_x4(b00, b01, b10, b11, ko + (uint32_t)(jp * 16 * PADK * 4));
                mma_tf32_b(s_[2 * jp],     qf[ks], b00, b01);
                mma_tf32_b(s_[2 * jp + 1], qf[ks], b10, b11);
            }
        }

        // ---- causal mask ----
        if (kt >= 2 * qt) {
            const int kb2 = kt * 64;
            const int r0 = qt * 128 + w16 + g, r1 = r0 + 8;
#pragma unroll
            for (int j = 0; j < 8; j++) {
                const int k0 = kb2 + j * 8 + 2 * q;
                if (k0 > r0)     s_[j][0] = -1e30f;
                if (k0 + 1 > r0) s_[j][1] = -1e30f;
                if (k0 > r1)     s_[j][2] = -1e30f;
                if (k0 + 1 > r1) s_[j][3] = -1e30f;
            }
        }

        // ---- online softmax ----
        float mx0 = -1e30f, mx1 = -1e30f;
#pragma unroll
        for (int j = 0; j < 8; j++) {
            mx0 = fmaxf(mx0, fmaxf(s_[j][0], s_[j][1]));
            mx1 = fmaxf(mx1, fmaxf(s_[j][2], s_[j][3]));
        }
        mx0 = fmaxf(mx0, __shfl_xor_sync(0xffffffffu, mx0, 1));
        mx0 = fmaxf(mx0, __shfl_xor_sync(0xffffffffu, mx0, 2));
        mx1 = fmaxf(mx1, __shfl_xor_sync(0xffffffffu, mx1, 1));
        mx1 = fmaxf(mx1, __shfl_xor_sync(0xffffffffu, mx1, 2));

        const float mn0 = fmaxf(m0, mx0), mn1 = fmaxf(m1, mx1);
        const float ex0 = __expf(m0 - mn0), ex1 = __expf(m1 - mn1);
        float rs0 = 0.f, rs1 = 0.f;
#pragma unroll
        for (int j = 0; j < 8; j++) {
            s_[j][0] = rna_tf32(__expf(s_[j][0] - mn0));
            s_[j][1] = rna_tf32(__expf(s_[j][1] - mn0));
            s_[j][2] = rna_tf32(__expf(s_[j][2] - mn1));
            s_[j][3] = rna_tf32(__expf(s_[j][3] - mn1));
            rs0 += s_[j][0] + s_[j][1];
            rs1 += s_[j][2] + s_[j][3];
        }
        rs0 += __shfl_xor_sync(0xffffffffu, rs0, 1);
        rs0 += __shfl_xor_sync(0xffffffffu, rs0, 2);
        rs1 += __shfl_xor_sync(0xffffffffu, rs1, 1);
        rs1 += __shfl_xor_sync(0xffffffffu, rs1, 2);
        l0 = l0 * ex0 + rs0;  m0 = mn0;
        l1 = l1 * ex1 + rs1;  m1 = mn1;
#pragma unroll
        for (int j = 0; j < 8; j++) {
            o_[j][0] *= ex0; o_[j][1] *= ex0;
            o_[j][2] *= ex1; o_[j][3] *= ex1;
        }

        // ---- O += P V (C-fragment direct; V rows permuted) ----
        const float* Vb = Vs + s * VS_F;
#pragma unroll
        for (int ks = 0; ks < 8; ks++) {
            uint32_t a[4];
            a[0] = __float_as_uint(s_[ks][0]);
            a[1] = __float_as_uint(s_[ks][2]);
            a[2] = __float_as_uint(s_[ks][1]);
            a[3] = __float_as_uint(s_[ks][3]);
            const float* Vr0 = Vb + (ks * 8 + q) * PADV + g;
            const float* Vr1 = Vb + (ks * 8 + q + 4) * PADV + g;
#pragma unroll
            for (int j = 0; j < 8; j++) {
                const uint32_t b0 = __float_as_uint(Vr0[j * 8]);
                const uint32_t b1 = __float_as_uint(Vr1[j * 8]);
                mma_tf32_b(o_[j], a, b0, b1);
            }
        }
    }

    // ---- epilogue ----
    const int b = bh >> 4, h = bh & 15;
    const float inv0 = 1.f / l0, inv1 = 1.f / l1;
    const int t0 = qt * 128 + w16 + g;
    float* dst0 = g_o + ((size_t)(b * T_ + t0)) * D_ + h * 64;
    float* dst1 = g_o + ((size_t)(b * T_ + t0 + 8)) * D_ + h * 64;
#pragma unroll
    for (int j = 0; j < 8; j++) {
        *(float2*)(dst0 + j * 8 + 2 * q) =
            make_float2(rna_tf32(o_[j][0] * inv0), rna_tf32(o_[j][1] * inv0));
        *(float2*)(dst1 + j * 8 + 2 * q) =
            make_float2(rna_tf32(o_[j][2] * inv1), rna_tf32(o_[j][3] * inv1));
    }
}

// ---------------------------------------------------------------------------
// Launch
// ---------------------------------------------------------------------------
extern "C" void kernel_launch(void* const* d_in, const int* in_sizes, int n_in,
                              void* d_out, int out_size) {
    const float* x  = (const float*)d_in[0];
    const float* Wk = (const float*)d_in[1];
    const float* Wq = (const float*)d_in[2];
    const float* Wv = (const float*)d_in[3];
    const float* Wp = (const float*)d_in[4];
    const float* bp = (const float*)d_in[5];
    float* out = (float*)d_out;

    float *qp, *kp, *vp, *op, *xr, *wr;
    cudaGetSymbolAddress((void**)&qp, g_q);
    cudaGetSymbolAddress((void**)&kp, g_k);
    cudaGetSymbolAddress((void**)&vp, g_v);
    cudaGetSymbolAddress((void**)&op, g_o);
    cudaGetSymbolAddress((void**)&xr, g_xr);
    cudaGetSymbolAddress((void**)&wr, g_wr);

    cudaFuncSetAttribute(gemm_qkv, cudaFuncAttributeMaxDynamicSharedMemorySize, GSMEM);
    cudaFuncSetAttribute(gemm_out, cudaFuncAttributeMaxDynamicSharedMemorySize, GSMEM);
    cudaFuncSetAttribute(flash_mma, cudaFuncAttributeMaxDynamicSharedMemorySize, FL_SMEM);

    const int NX = B_ * T_ * D_;
    const int NW = D_ * D_;

    // rounding
    round_tf32<<<NX / 1024, 256>>>(x, xr);
    WPtrs ws; ws.w[0] = Wk; ws.w[1] = Wq; ws.w[2] = Wv; ws.w[3] = Wp;
    round_w4<<<dim3(NW / 1024, 4), 256>>>(ws, wr);

    // fused QKV projections
    gemm_qkv<<<dim3(D_ / 128, M_ / 128, 3), 128, GSMEM>>>(xr, wr, kp, qp, vp);

    // flash attention v6
    flash_mma<<<dim3(T_ / 128, B_ * H_), 256, FL_SMEM>>>();

    // output projection
    gemm_out<<<dim3(D_ / 128, M_ / 128), 128, GSMEM>>>(op, wr + 3 * (size_t)NW, out, bp);
}

// round 16
// speedup vs baseline: 1.3093x; 1.0454x over previous
#include <cuda_runtime.h>
#include <cstdint>

// Problem constants
#define B_  4
#define T_  2048
#define D_  1024
#define H_  16
#define HD_ 64
#define M_  (B_*T_)   // 8192

// Scratch buffers
__device__ float g_q[(size_t)B_*H_*T_*HD_];
__device__ float g_k[(size_t)B_*H_*T_*HD_];
__device__ float g_v[(size_t)B_*H_*T_*HD_];
__device__ float g_o[(size_t)B_*T_*D_];
__device__ float g_xr[(size_t)B_*T_*D_];     // tf32-rounded activations
__device__ float g_wr[(size_t)4*D_*D_];      // tf32-rounded weights (k,q,v,p)

// ---------------------------------------------------------------------------
// helpers
// ---------------------------------------------------------------------------
__device__ __forceinline__ uint32_t smem_u32(const void* p) {
    uint32_t a;
    asm("{ .reg .u64 t; cvta.to.shared.u64 t, %1; cvt.u32.u64 %0, t; }"
        : "=r"(a) : "l"(p));
    return a;
}

__device__ __forceinline__ void cp_async16(uint32_t dst, const void* src) {
    asm volatile("cp.async.cg.shared.global [%0], [%1], 16;" :: "r"(dst), "l"(src));
}

// ldmatrix x4: four 8x8 b16 matrices == tf32 fragments (1 tf32/lane/matrix).
__device__ __forceinline__ void ldsm_x4(uint32_t& r0, uint32_t& r1,
                                        uint32_t& r2, uint32_t& r3, uint32_t addr) {
    asm volatile("ldmatrix.sync.aligned.m8n8.x4.shared.b16 {%0,%1,%2,%3}, [%4];"
                 : "=r"(r0), "=r"(r1), "=r"(r2), "=r"(r3) : "r"(addr));
}

__device__ __forceinline__ void mma_tf32_b(float* c, const uint32_t* a,
                                           uint32_t b0, uint32_t b1) {
    asm volatile(
        "mma.sync.aligned.m16n8k8.row.col.f32.tf32.tf32.f32 "
        "{%0,%1,%2,%3}, {%4,%5,%6,%7}, {%8,%9}, {%0,%1,%2,%3};"
        : "+f"(c[0]), "+f"(c[1]), "+f"(c[2]), "+f"(c[3])
        : "r"(a[0]), "r"(a[1]), "r"(a[2]), "r"(a[3]), "r"(b0), "r"(b1));
}

__device__ __forceinline__ float rna_tf32(float x) {
    uint32_t u;
    asm("cvt.rna.tf32.f32 %0, %1;" : "=r"(u) : "f"(x));
    return __uint_as_float(u);
}

// ---------------------------------------------------------------------------
// tf32 pre-rounding
// ---------------------------------------------------------------------------
__global__ void __launch_bounds__(256) round_tf32(const float* __restrict__ x,
                                                  float* __restrict__ y) {
    const size_t i = ((size_t)blockIdx.x * 256 + threadIdx.x) * 4;
    float4 v = *(const float4*)(x + i);
    float4 o;
    o.x = rna_tf32(v.x); o.y = rna_tf32(v.y);
    o.z = rna_tf32(v.z); o.w = rna_tf32(v.w);
    *(float4*)(y + i) = o;
}

struct WPtrs { const float* w[4]; };
__global__ void __launch_bounds__(256) round_w4(WPtrs ws, float* __restrict__ y) {
    const int z = blockIdx.y;
    const float* src = ws.w[z];
    float* dst = y + (size_t)z * D_ * D_;
    const size_t i = ((size_t)blockIdx.x * 256 + threadIdx.x) * 4;
    float4 v = *(const float4*)(src + i);
    float4 o;
    o.x = rna_tf32(v.x); o.y = rna_tf32(v.y);
    o.z = rna_tf32(v.z); o.w = rna_tf32(v.w);
    *(float4*)(dst + i) = o;
}

// ---------------------------------------------------------------------------
// GEMM v3: 256 threads, 8 warps (2x4), warp tile 64x32 -> 4 warps/SMSP.
// ldmatrix fragment loads, 3-stage cp.async, 2 CTAs/SM.
// ---------------------------------------------------------------------------
#define SROW   36
#define STG_F  (128 * SROW)
#define STAGE_F (2 * STG_F)
#define GSMEM  (3 * STAGE_F * 4)   // 110592 B

template<int MODE>
__device__ __forceinline__ void gemm_body(const float* __restrict__ A,
                                          const float* __restrict__ W,
                                          float* __restrict__ out,
                                          const float* __restrict__ bias,
                                          float* sm, int bx, int by) {
    const int tid  = threadIdx.x;
    const int lane = tid & 31;
    const int wid  = tid >> 5;
    const int wm   = wid >> 2;       // 0..1
    const int wn   = wid & 3;        // 0..3

    float c[4][4][4];
#pragma unroll
    for (int i = 0; i < 4; i++)
#pragma unroll
        for (int j = 0; j < 4; j++)
#pragma unroll
            for (int k = 0; k < 4; k++) c[i][j][k] = 0.f;

    // gmem->smem: 256 threads, 4x16B for A + 4x16B for B per stage
    const int lr = tid >> 3;     // 0..31
    const int ls = tid & 7;
    const float* Ag = A + (size_t)(by * 128 + lr) * 1024 + ls * 4;
    const float* Wg = W + (size_t)(bx * 128 + lr) * 1024 + ls * 4;

    const uint32_t sbase = smem_u32(sm);
    const uint32_t ldst  = sbase + (lr * SROW + ls * 4) * 4;

    auto load_tile = [&](int kt, int s) {
        const uint32_t aB = ldst + (uint32_t)s * (STAGE_F * 4);
        const uint32_t bB = aB + STG_F * 4;
        const float* Ak = Ag + kt * 32;
        const float* Wk = Wg + kt * 32;
#pragma unroll
        for (int i = 0; i < 4; i++) {
            cp_async16(aB + i * 32 * (SROW * 4), Ak + (size_t)i * 32 * 1024);
            cp_async16(bB + i * 32 * (SROW * 4), Wk + (size_t)i * 32 * 1024);
        }
        asm volatile("cp.async.commit_group;" ::: "memory");
    };

    load_tile(0, 0);
    load_tile(1, 1);

    // ldmatrix base offsets (proven mappings from round 15)
    const uint32_t aOff = (uint32_t)(((wm * 64 + (lane & 15)) * SROW +
                                      ((lane >> 4) << 2)) * 4);
    const uint32_t bOff = (uint32_t)((STG_F + ((wn * 32 + (lane & 7) +
                                      ((lane >> 4) << 3)) * SROW) +
                                      (((lane >> 3) & 1) << 2)) * 4);

    const int q = lane & 3;
    const int g = lane >> 2;

    int s = 0, sl = 2;
    for (int kt = 0; kt < 32; kt++) {
        if (kt < 31) {
            asm volatile("cp.async.wait_group 1;" ::: "memory");
        } else {
            asm volatile("cp.async.wait_group 0;" ::: "memory");
        }
        __syncthreads();

        if (kt + 2 < 32) {
            load_tile(kt + 2, sl);
            sl = (sl == 2) ? 0 : sl + 1;
        }

        const uint32_t stB = sbase + (uint32_t)s * (STAGE_F * 4);
#pragma unroll
        for (int ks = 0; ks < 4; ks++) {
            const uint32_t ko = (uint32_t)(ks * 8 * 4);
            uint32_t af[4][4], bf[2][4];
#pragma unroll
            for (int mm = 0; mm < 4; mm++)
                ldsm_x4(af[mm][0], af[mm][1], af[mm][2], af[mm][3],
                        stB + aOff + (uint32_t)(mm * 16 * SROW * 4) + ko);
#pragma unroll
            for (int np = 0; np < 2; np++)
                ldsm_x4(bf[np][0], bf[np][1], bf[np][2], bf[np][3],
                        stB + bOff + (uint32_t)(np * 16 * SROW * 4) + ko);
#pragma unroll
            for (int mm = 0; mm < 4; mm++)
#pragma unroll
                for (int np = 0; np < 2; np++) {
                    mma_tf32_b(c[mm][2 * np],     af[mm], bf[np][0], bf[np][1]);
                    mma_tf32_b(c[mm][2 * np + 1], af[mm], bf[np][2], bf[np][3]);
                }
        }
        s = (s == 2) ? 0 : s + 1;
    }

    const int rbase = by * 128 + wm * 64 + g;
    const int cbase = bx * 128 + wn * 32 + 2 * q;
#pragma unroll
    for (int mm = 0; mm < 4; mm++) {
        const int r0 = rbase + mm * 16;
#pragma unroll
        for (int nn = 0; nn < 4; nn++) {
            const int cc = cbase + nn * 8;
            if (MODE == 0) {
                const int h = cc >> 6, d = cc & 63;
                const int b = r0 >> 11, t = r0 & 2047;
                float* dst = out + (((size_t)(b * H_ + h)) * T_ + t) * HD_ + d;
                *(float2*)dst =
                    make_float2(rna_tf32(c[mm][nn][0]), rna_tf32(c[mm][nn][1]));
                *(float2*)(dst + 8 * HD_) =
                    make_float2(rna_tf32(c[mm][nn][2]), rna_tf32(c[mm][nn][3]));
            } else {
                float2 bb = *(const float2*)(bias + cc);
                float* dst = out + (size_t)r0 * 1024 + cc;
                *(float2*)dst = make_float2(c[mm][nn][0] + bb.x, c[mm][nn][1] + bb.y);
                *(float2*)(dst + 8 * 1024) =
                    make_float2(c[mm][nn][2] + bb.x, c[mm][nn][3] + bb.y);
            }
        }
    }
}

__global__ void __launch_bounds__(256, 2) gemm_qkv(const float* __restrict__ A,
                                                   const float* __restrict__ Wr,
                                                   float* __restrict__ o0,
                                                   float* __restrict__ o1,
                                                   float* __restrict__ o2) {
    extern __shared__ float sm[];
    const int z = blockIdx.z;
    const float* W = Wr + (size_t)z * D_ * D_;
    float* out = (z == 0) ? o0 : (z == 1) ? o1 : o2;
    gemm_body<0>(A, W, out, nullptr, sm, blockIdx.x, blockIdx.y);
}

__global__ void __launch_bounds__(256, 2) gemm_out(const float* __restrict__ A,
                                                   const float* __restrict__ W,
                                                   float* __restrict__ out,
                                                   const float* __restrict__ bias) {
    extern __shared__ float sm[];
    gemm_body<1>(A, W, out, bias, sm, blockIdx.x, blockIdx.y);
}

// ---------------------------------------------------------------------------
// Flash attention v6 (unchanged — known good)
// smem: Ks[3][64*68] + Vs[3][64*72] = 107520 B -> 2 CTAs/SM.
// ---------------------------------------------------------------------------
#define PADK 68
#define PADV 72
#define KS_F (64 * PADK)
#define VS_F (64 * PADV)
#define FL_SMEM ((3 * KS_F + 3 * VS_F) * 4)   // 107520

__global__ void __launch_bounds__(256, 2) flash_mma() {
    extern __shared__ float sm[];
    float* Vs = sm + 3 * KS_F;
    float* Qstage = Vs + VS_F;

    const int tid = threadIdx.x, lane = tid & 31, wid = tid >> 5;
    const int g = lane >> 2, q = lane & 3;
    const int qt = blockIdx.x, bh = blockIdx.y;
    const int w16 = wid * 16;

    const float* Qg = g_q + (size_t)bh * T_ * HD_ + (size_t)qt * 128 * HD_;
    const float* Kg = g_k + (size_t)bh * T_ * HD_;
    const float* Vg = g_v + (size_t)bh * T_ * HD_;

    const uint32_t sb  = smem_u32(sm);
    const uint32_t VsB = sb + 3 * KS_F * 4;
    const uint32_t QsB = VsB + VS_F * 4;

    const int lrow = tid >> 4;
    const int lchk = tid & 15;

    auto load_kv = [&](int kt, int s) {
        const float* Kt = Kg + (size_t)kt * 64 * 64;
        const float* Vt = Vg + (size_t)kt * 64 * 64;
        const uint32_t kB = sb + (uint32_t)s * (KS_F * 4);
        const uint32_t vB = VsB + (uint32_t)s * (VS_F * 4);
#pragma unroll
        for (int i = 0; i < 4; i++) {
            const int r = lrow + i * 16;
            const int pr = (r & 56) | ((r & 1) << 2) | ((r >> 1) & 3);
            cp_async16(kB + (r * PADK + lchk * 4) * 4, Kt + r * 64 + lchk * 4);
            cp_async16(vB + (pr * PADV + lchk * 4) * 4, Vt + r * 64 + lchk * 4);
        }
        asm volatile("cp.async.commit_group;" ::: "memory");
    };

    // ---- prologue ----
    {
        const int row = tid >> 1, segb = (tid & 1) * 8;
#pragma unroll
        for (int i = 0; i < 8; i++)
            cp_async16(QsB + (row * PADK + (segb + i) * 4) * 4,
                       Qg + row * 64 + (segb + i) * 4);
        asm volatile("cp.async.commit_group;" ::: "memory");
    }
    load_kv(0, 0);
    asm volatile("cp.async.wait_group 1;" ::: "memory");
    __syncthreads();

    uint32_t qf[8][4];
#pragma unroll
    for (int ks = 0; ks < 8; ks++) {
        qf[ks][0] = __float_as_uint(Qstage[(w16 + g) * PADK + ks * 8 + q] * 0.125f);
        qf[ks][1] = __float_as_uint(Qstage[(w16 + g + 8) * PADK + ks * 8 + q] * 0.125f);
        qf[ks][2] = __float_as_uint(Qstage[(w16 + g) * PADK + ks * 8 + q + 4] * 0.125f);
        qf[ks][3] = __float_as_uint(Qstage[(w16 + g + 8) * PADK + ks * 8 + q + 4] * 0.125f);
    }
    __syncthreads();
    const int nkt = 2 * qt + 2;
    load_kv(1, 1);

    const uint32_t kOff = (uint32_t)((((lane & 7) + ((lane >> 4) << 3)) * PADK +
                                      (((lane >> 3) & 1) << 2)) * 4);

    float o_[8][4];
#pragma unroll
    for (int j = 0; j < 8; j++)
#pragma unroll
        for (int k = 0; k < 4; k++) o_[j][k] = 0.f;
    float m0 = -1e30f, m1 = -1e30f, l0 = 0.f, l1 = 0.f;

    for (int kt = 0; kt < nkt; kt++) {
        const int s = kt % 3;

        asm volatile("cp.async.wait_group 1;" ::: "memory");
        __syncthreads();
        if (kt + 2 < nkt) load_kv(kt + 2, (kt + 2) % 3);

        // ---- S = Q K^T (K fragments via ldmatrix) ----
        float s_[8][4];
#pragma unroll
        for (int j = 0; j < 8; j++)
#pragma unroll
            for (int k = 0; k < 4; k++) s_[j][k] = 0.f;

        const uint32_t kStage = sb + (uint32_t)s * (KS_F * 4) + kOff;
#pragma unroll
        for (int ks = 0; ks < 8; ks++) {
            const uint32_t ko = kStage + (uint32_t)(ks * 8 * 4);
#pragma unroll
            for (int jp = 0; jp < 4; jp++) {
                uint32_t b00, b01, b10, b11;
                ldsm_x4(b00, b01, b10, b11, ko + (uint32_t)(jp * 16 * PADK * 4));
                mma_tf32_b(s_[2 * jp],     qf[ks], b00, b01);
                mma_tf32_b(s_[2 * jp + 1], qf[ks], b10, b11);
            }
        }

        // ---- causal mask ----
        if (kt >= 2 * qt) {
            const int kb2 = kt * 64;
            const int r0 = qt * 128 + w16 + g, r1 = r0 + 8;
#pragma unroll
            for (int j = 0; j < 8; j++) {
                const int k0 = kb2 + j * 8 + 2 * q;
                if (k0 > r0)     s_[j][0] = -1e30f;
                if (k0 + 1 > r0) s_[j][1] = -1e30f;
                if (k0 > r1)     s_[j][2] = -1e30f;
                if (k0 + 1 > r1) s_[j][3] = -1e30f;
            }
        }

        // ---- online softmax ----
        float mx0 = -1e30f, mx1 = -1e30f;
#pragma unroll
        for (int j = 0; j < 8; j++) {
            mx0 = fmaxf(mx0, fmaxf(s_[j][0], s_[j][1]));
            mx1 = fmaxf(mx1, fmaxf(s_[j][2], s_[j][3]));
        }
        mx0 = fmaxf(mx0, __shfl_xor_sync(0xffffffffu, mx0, 1));
        mx0 = fmaxf(mx0, __shfl_xor_sync(0xffffffffu, mx0, 2));
        mx1 = fmaxf(mx1, __shfl_xor_sync(0xffffffffu, mx1, 1));
        mx1 = fmaxf(mx1, __shfl_xor_sync(0xffffffffu, mx1, 2));

        const float mn0 = fmaxf(m0, mx0), mn1 = fmaxf(m1, mx1);
        const float ex0 = __expf(m0 - mn0), ex1 = __expf(m1 - mn1);
        float rs0 = 0.f, rs1 = 0.f;
#pragma unroll
        for (int j = 0; j < 8; j++) {
            s_[j][0] = rna_tf32(__expf(s_[j][0] - mn0));
            s_[j][1] = rna_tf32(__expf(s_[j][1] - mn0));
            s_[j][2] = rna_tf32(__expf(s_[j][2] - mn1));
            s_[j][3] = rna_tf32(__expf(s_[j][3] - mn1));
            rs0 += s_[j][0] + s_[j][1];
            rs1 += s_[j][2] + s_[j][3];
        }
        rs0 += __shfl_xor_sync(0xffffffffu, rs0, 1);
        rs0 += __shfl_xor_sync(0xffffffffu, rs0, 2);
        rs1 += __shfl_xor_sync(0xffffffffu, rs1, 1);
        rs1 += __shfl_xor_sync(0xffffffffu, rs1, 2);
        l0 = l0 * ex0 + rs0;  m0 = mn0;
        l1 = l1 * ex1 + rs1;  m1 = mn1;
#pragma unroll
        for (int j = 0; j < 8; j++) {
            o_[j][0] *= ex0; o_[j][1] *= ex0;
            o_[j][2] *= ex1; o_[j][3] *= ex1;
        }

        // ---- O += P V (C-fragment direct; V rows permuted) ----
        const float* Vb = Vs + s * VS_F;
#pragma unroll
        for (int ks = 0; ks < 8; ks++) {
            uint32_t a[4];
            a[0] = __float_as_uint(s_[ks][0]);
            a[1] = __float_as_uint(s_[ks][2]);
            a[2] = __float_as_uint(s_[ks][1]);
            a[3] = __float_as_uint(s_[ks][3]);
            const float* Vr0 = Vb + (ks * 8 + q) * PADV + g;
            const float* Vr1 = Vb + (ks * 8 + q + 4) * PADV + g;
#pragma unroll
            for (int j = 0; j < 8; j++) {
                const uint32_t b0 = __float_as_uint(Vr0[j * 8]);
                const uint32_t b1 = __float_as_uint(Vr1[j * 8]);
                mma_tf32_b(o_[j], a, b0, b1);
            }
        }
    }

    // ---- epilogue ----
    const int b = bh >> 4, h = bh & 15;
    const float inv0 = 1.f / l0, inv1 = 1.f / l1;
    const int t0 = qt * 128 + w16 + g;
    float* dst0 = g_o + ((size_t)(b * T_ + t0)) * D_ + h * 64;
    float* dst1 = g_o + ((size_t)(b * T_ + t0 + 8)) * D_ + h * 64;
#pragma unroll
    for (int j = 0; j < 8; j++) {
        *(float2*)(dst0 + j * 8 + 2 * q) =
            make_float2(rna_tf32(o_[j][0] * inv0), rna_tf32(o_[j][1] * inv0));
        *(float2*)(dst1 + j * 8 + 2 * q) =
            make_float2(rna_tf32(o_[j][2] * inv1), rna_tf32(o_[j][3] * inv1));
    }
}

// ---------------------------------------------------------------------------
// Launch
// ---------------------------------------------------------------------------
extern "C" void kernel_launch(void* const* d_in, const int* in_sizes, int n_in,
                              void* d_out, int out_size) {
    const float* x  = (const float*)d_in[0];
    const float* Wk = (const float*)d_in[1];
    const float* Wq = (const float*)d_in[2];
    const float* Wv = (const float*)d_in[3];
    const float* Wp = (const float*)d_in[4];
    const float* bp = (const float*)d_in[5];
    float* out = (float*)d_out;

    float *qp, *kp, *vp, *op, *xr, *wr;
    cudaGetSymbolAddress((void**)&qp, g_q);
    cudaGetSymbolAddress((void**)&kp, g_k);
    cudaGetSymbolAddress((void**)&vp, g_v);
    cudaGetSymbolAddress((void**)&op, g_o);
    cudaGetSymbolAddress((void**)&xr, g_xr);
    cudaGetSymbolAddress((void**)&wr, g_wr);

    cudaFuncSetAttribute(gemm_qkv, cudaFuncAttributeMaxDynamicSharedMemorySize, GSMEM);
    cudaFuncSetAttribute(gemm_out, cudaFuncAttributeMaxDynamicSharedMemorySize, GSMEM);
    cudaFuncSetAttribute(flash_mma, cudaFuncAttributeMaxDynamicSharedMemorySize, FL_SMEM);

    const int NX = B_ * T_ * D_;
    const int NW = D_ * D_;

    // rounding
    round_tf32<<<NX / 1024, 256>>>(x, xr);
    WPtrs ws; ws.w[0] = Wk; ws.w[1] = Wq; ws.w[2] = Wv; ws.w[3] = Wp;
    round_w4<<<dim3(NW / 1024, 4), 256>>>(ws, wr);

    // fused QKV projections (8-warp GEMM)
    gemm_qkv<<<dim3(D_ / 128, M_ / 128, 3), 256, GSMEM>>>(xr, wr, kp, qp, vp);

    // flash attention v6
    flash_mma<<<dim3(T_ / 128, B_ * H_), 256, FL_SMEM>>>();

    // output projection
    gemm_out<<<dim3(D_ / 128, M_ / 128), 256, GSMEM>>>(op, wr + 3 * (size_t)NW, out, bp);
}